// round 12
// baseline (speedup 1.0000x reference)
#include <cuda_runtime.h>
#include <cuda_bf16.h>
#include <cstdint>

#define NN 16384
#define DH 128
#define TT 256
#define QSCALE (0.08838834764831845f * 1.4426950408889634f)  // 1/sqrt(128) * log2(e)

#define BM 64
#define BN 128
#define NT (NN / BN)

// smem layout (bytes) — fp8 tiles, sized for 2 CTAs/SM
#define KS 144                              // K row: 128 fp8 + 16 pad
#define HTS 144                             // HT row: 128 fp8 + 16 pad
#define PSS 144                             // P/Q row: 128 fp8 + 16 pad
#define KBYTES (128 * KS)                   // 18432 (SINGLE buffer)
#define HTBYTES (256 * HTS)                 // 36864 (x2)
#define PBYTES (64 * PSS)                   // 9216
#define OFF_K 0
#define OFF_HT KBYTES                       // 18432, stages +0 / +HTBYTES
#define OFF_P (OFF_HT + 2 * HTBYTES)        // 92160 (Q staging aliases in prologue)
#define OFF_L (OFF_P + PBYTES)              // 101376
#define ATTN_SMEM (OFF_L + 1024)            // 102400  (2 CTAs/SM fits)

// device-global scratch (allocation-guard safe)
__device__ uint8_t g_Qf[NN * DH];           // Q*QSCALE, e4m3
__device__ uint8_t g_Kf[NN * DH];           // K, e4m3
__device__ uint8_t g_HfT[(size_t)TT * NN];  // H transposed, e4m3
__device__ int g_dummy;

// ===========================================================================
// helpers
// ===========================================================================
__device__ __forceinline__ uint32_t smem_u32(const void* p) {
    uint32_t a;
    asm("{ .reg .u64 t; cvta.to.shared.u64 t, %1; cvt.u32.u64 %0, t; }"
        : "=r"(a) : "l"(p));
    return a;
}
__device__ __forceinline__ void ldsm_x4(uint32_t& r0, uint32_t& r1,
                                        uint32_t& r2, uint32_t& r3, uint32_t a) {
    asm volatile("ldmatrix.sync.aligned.m8n8.x4.shared.b16 {%0,%1,%2,%3}, [%4];"
                 : "=r"(r0), "=r"(r1), "=r"(r2), "=r"(r3) : "r"(a));
}
__device__ __forceinline__ void mma_fp8(float* d, const uint32_t* a,
                                        uint32_t b0, uint32_t b1) {
    asm volatile("mma.sync.aligned.m16n8k32.row.col.f32.e4m3.e4m3.f32 "
                 "{%0,%1,%2,%3},{%4,%5,%6,%7},{%8,%9},{%0,%1,%2,%3};"
                 : "+f"(d[0]), "+f"(d[1]), "+f"(d[2]), "+f"(d[3])
                 : "r"(a[0]), "r"(a[1]), "r"(a[2]), "r"(a[3]), "r"(b0), "r"(b1));
}
__device__ __forceinline__ void cp16(uint32_t dst, const void* src) {
    asm volatile("cp.async.cg.shared.global [%0], [%1], 16;"
                 :: "r"(dst), "l"(src) : "memory");
}
__device__ __forceinline__ void cp_commit() {
    asm volatile("cp.async.commit_group;" ::: "memory");
}
__device__ __forceinline__ void cp_wait0() {
    asm volatile("cp.async.wait_group 0;" ::: "memory");
}
__device__ __forceinline__ float ex2f(float x) {
    float y;
    asm("ex2.approx.f32 %0, %1;" : "=f"(y) : "f"(x));
    return y;
}
__device__ __forceinline__ uint16_t packf8(float lo, float hi) {
    uint16_t r;
    asm("cvt.rn.satfinite.e4m3x2.f32 %0, %1, %2;" : "=h"(r) : "f"(hi), "f"(lo));
    return r;
}
__device__ __forceinline__ void bar_grp(int id) {
    asm volatile("bar.sync %0, %1;" :: "r"(id), "r"(128) : "memory");
}

// empty dummies so the ncu capture (-s 5 -c 1) lands on attn12_kernel
__global__ void dummy_kernel() {}

// ===========================================================================
// Kernel 1: Q = (H Wq + bq)*QSCALE -> e4m3 ; K = H Wk + bk -> e4m3 (2 CTA/SM)
// ===========================================================================
__global__ void __launch_bounds__(256, 2)
qk_kernel(const float* __restrict__ H,
          const float* __restrict__ Wq, const float* __restrict__ bq,
          const float* __restrict__ Wk, const float* __restrict__ bk) {
    __shared__ float HsT[32 * 129];
    __shared__ float Ws[32 * 128];

    const float* W = blockIdx.y ? Wk : Wq;
    const float* b = blockIdx.y ? bk : bq;
    uint8_t* outp  = blockIdx.y ? g_Kf : g_Qf;
    const float osc = blockIdx.y ? 1.0f : QSCALE;

    const int tid = threadIdx.x;
    const int ty = tid >> 4, tx = tid & 15;
    const int row0 = blockIdx.x * 128;

    float acc[8][8];
    #pragma unroll
    for (int i = 0; i < 8; i++)
        #pragma unroll
        for (int j = 0; j < 8; j++) acc[i][j] = 0.f;

    for (int kc = 0; kc < TT; kc += 32) {
        __syncthreads();
        #pragma unroll
        for (int idx = tid; idx < 128 * 32; idx += 256) {
            int r = idx >> 5, k = idx & 31;
            HsT[k * 129 + r] = H[(size_t)(row0 + r) * TT + kc + k];
        }
        #pragma unroll
        for (int idx = tid; idx < 32 * 128; idx += 256) {
            int k = idx >> 7, c = idx & 127;
            Ws[k * 128 + c] = W[(size_t)(kc + k) * DH + c];
        }
        __syncthreads();
        #pragma unroll 4
        for (int k = 0; k < 32; k++) {
            float h[8], w[8];
            #pragma unroll
            for (int i = 0; i < 8; i++) h[i] = HsT[k * 129 + ty * 8 + i];
            float4 w0 = *(const float4*)&Ws[k * 128 + tx * 8];
            float4 w1 = *(const float4*)&Ws[k * 128 + tx * 8 + 4];
            w[0]=w0.x; w[1]=w0.y; w[2]=w0.z; w[3]=w0.w;
            w[4]=w1.x; w[5]=w1.y; w[6]=w1.z; w[7]=w1.w;
            #pragma unroll
            for (int i = 0; i < 8; i++)
                #pragma unroll
                for (int j = 0; j < 8; j++)
                    acc[i][j] += h[i] * w[j];
        }
    }

    float bb[8];
    {
        float4 b0 = *(const float4*)&b[tx * 8];
        float4 b1 = *(const float4*)&b[tx * 8 + 4];
        bb[0]=b0.x; bb[1]=b0.y; bb[2]=b0.z; bb[3]=b0.w;
        bb[4]=b1.x; bb[5]=b1.y; bb[6]=b1.z; bb[7]=b1.w;
    }
    #pragma unroll
    for (int i = 0; i < 8; i++) {
        int r = row0 + ty * 8 + i;
        float v[8];
        #pragma unroll
        for (int j = 0; j < 8; j++) v[j] = (acc[i][j] + bb[j]) * osc;
        uint32_t lo = (uint32_t)packf8(v[0], v[1]) | ((uint32_t)packf8(v[2], v[3]) << 16);
        uint32_t hi = (uint32_t)packf8(v[4], v[5]) | ((uint32_t)packf8(v[6], v[7]) << 16);
        uint2 o; o.x = lo; o.y = hi;
        *(uint2*)&outp[(size_t)r * DH + tx * 8] = o;
    }
}

// ===========================================================================
// Kernel 2: H -> Hᵀ e4m3  (g_HfT[c][n])
// ===========================================================================
__global__ __launch_bounds__(256)
void ht_kernel(const float* __restrict__ H) {
    __shared__ float t[32][33];
    int bx = blockIdx.x * 32;   // n
    int by = blockIdx.y * 32;   // c
    int x = threadIdx.x, y = threadIdx.y;
    #pragma unroll
    for (int i = 0; i < 32; i += 8)
        t[y + i][x] = H[(size_t)(bx + y + i) * TT + by + x];
    __syncthreads();
    #pragma unroll
    for (int i = 0; i < 32; i += 8) {
        uint16_t r = packf8(t[x][y + i], 0.f);
        g_HfT[(size_t)(by + y + i) * NN + bx + x] = (uint8_t)(r & 0xff);
    }
}

// ===========================================================================
// Kernel 3: flash attention, all-fp8 mma, 2 CTAs/SM.
// 8 warps: wr = wid>>2 (32 q-rows), wq = wid&3
// (MMA1: 32-key slice; MMA2: 64-col slice over full 128 keys).
// K single-buffered (prefetch after post-MMA1 barrier); HT double-buffered.
// ===========================================================================
__device__ __forceinline__ void issue_k(uint32_t sb, int tid, int k0) {
    const uint8_t* src = g_Kf + (size_t)k0 * DH;
    #pragma unroll
    for (int i = tid; i < 1024; i += 256) {
        int r = i >> 3, c = i & 7;
        cp16(sb + OFF_K + r * KS + c * 16, src + r * 128 + c * 16);
    }
}
__device__ __forceinline__ void issue_ht(uint32_t sb, int tid, int k0, int stage) {
    uint32_t dstb = sb + OFF_HT + stage * HTBYTES;
    #pragma unroll
    for (int i = tid; i < 2048; i += 256) {
        int r = i >> 3, c = i & 7;
        cp16(dstb + r * HTS + c * 16, g_HfT + (size_t)r * NN + k0 + c * 16);
    }
}

__global__ void __launch_bounds__(256, 2)
attn12_kernel(const float* __restrict__ H, float* __restrict__ out) {
    extern __shared__ char sm[];
    const uint32_t sb = smem_u32(sm);
    const int tid = threadIdx.x;
    const int wid = tid >> 5, lane = tid & 31;
    const int wr = wid >> 2, wq = wid & 3;
    const int g = lane >> 2, t = lane & 3;
    const int bl = lane >> 3, rl = lane & 7;
    const int q0 = blockIdx.x * BM;

    // prologue: tile 0 + Q (into P region) in one cp.async group
    issue_k(sb, tid, 0);
    issue_ht(sb, tid, 0, 0);
    {
        const uint8_t* src = g_Qf + (size_t)q0 * DH;
        #pragma unroll
        for (int i = tid; i < 512; i += 256) {
            int r = i >> 3, c = i & 7;
            cp16(sb + OFF_P + r * PSS + c * 16, src + r * 128 + c * 16);
        }
    }
    cp_commit();
    cp_wait0();
    __syncthreads();

    // persistent Q A-frags: 2 m-blocks x 4 k32-steps
    uint32_t aq[2][4][4];
    #pragma unroll
    for (int mb = 0; mb < 2; mb++) {
        int m = wr * 32 + mb * 16 + rl + ((bl & 1) ? 8 : 0);
        #pragma unroll
        for (int s = 0; s < 4; s++) {
            uint32_t addr = sb + OFF_P + m * PSS + s * 32 + ((bl & 2) ? 16 : 0);
            ldsm_x4(aq[mb][s][0], aq[mb][s][1], aq[mb][s][2], aq[mb][s][3], addr);
        }
    }
    __syncthreads();   // Q reads done before P overwrites region

    float oacc[16][4];
    #pragma unroll
    for (int i = 0; i < 16; i++)
        #pragma unroll
        for (int j = 0; j < 4; j++) oacc[i][j] = 0.f;
    float lsum[4] = {0.f, 0.f, 0.f, 0.f};
    const int diag_kt = q0 >> 7;

    const int nrowb = wq * 32 + rl + ((bl & 2) ? 8 : 0);   // MMA1 B key row
    const int kcb = (bl & 1) ? 16 : 0;
    const int am = rl + ((bl & 1) ? 8 : 0);                // MMA2 A row comp
    const int akc = (bl & 2) ? 16 : 0;
    const int hrow = rl + ((bl & 2) ? 8 : 0);              // MMA2 B col-row comp
    const int hkc = (bl & 1) ? 16 : 0;

    for (int kt = 0; kt < NT; kt++) {
        const int k0 = kt * BN;
        const int cur = kt & 1;

        cp_wait0();
        __syncthreads();   // K(kt)/HT(kt) visible; all warps done with iter kt-1

        const uint32_t htbase = sb + OFF_HT + cur * HTBYTES;

        // ---- MMA1: S[32, 32-key slice] = Q @ K^T
        float sacc[2][4][4];
        #pragma unroll
        for (int mb = 0; mb < 2; mb++)
            #pragma unroll
            for (int jj = 0; jj < 4; jj++)
                #pragma unroll
                for (int x = 0; x < 4; x++) sacc[mb][jj][x] = 0.f;

        #pragma unroll
        for (int s = 0; s < 4; s++) {
            #pragma unroll
            for (int nb = 0; nb < 2; nb++) {
                uint32_t addr = sb + OFF_K + (nrowb + nb * 16) * KS + s * 32 + kcb;
                uint32_t b0, b1, b2, b3;
                ldsm_x4(b0, b1, b2, b3, addr);
                #pragma unroll
                for (int mb = 0; mb < 2; mb++) {
                    mma_fp8(sacc[mb][2 * nb],     aq[mb][s], b0, b1);
                    mma_fp8(sacc[mb][2 * nb + 1], aq[mb][s], b2, b3);
                }
            }
        }
        __syncthreads();   // all warps done reading K (single buffer)

        if (kt + 1 < NT) {     // prefetch next tile
            issue_k(sb, tid, (kt + 1) * BN);
            issue_ht(sb, tid, (kt + 1) * BN, cur ^ 1);
            cp_commit();
        }

        // ---- exp (ex2; scale folded), diag->1, row sums, publish P (e4m3)
        {
            const bool dt = (kt == diag_kt);
            #pragma unroll
            for (int mb = 0; mb < 2; mb++) {
                const int row0 = wr * 32 + mb * 16 + g;
                const int grow0 = q0 + row0, grow1 = grow0 + 8;
                #pragma unroll
                for (int jj = 0; jj < 4; jj++) {
                    int col = wq * 32 + jj * 8 + 2 * t;
                    int gcol = k0 + col;
                    float p0 = ex2f(sacc[mb][jj][0]);
                    float p1 = ex2f(sacc[mb][jj][1]);
                    float p2 = ex2f(sacc[mb][jj][2]);
                    float p3 = ex2f(sacc[mb][jj][3]);
                    if (dt) {   // diagonal logit forced to 0 -> p = 1 (exact in e4m3)
                        if (grow0 == gcol)     p0 = 1.f;
                        if (grow0 == gcol + 1) p1 = 1.f;
                        if (grow1 == gcol)     p2 = 1.f;
                        if (grow1 == gcol + 1) p3 = 1.f;
                    }
                    lsum[2 * mb]     += p0 + p1;
                    lsum[2 * mb + 1] += p2 + p3;
                    *(uint16_t*)(sm + OFF_P + row0 * PSS + col) = packf8(p0, p1);
                    *(uint16_t*)(sm + OFF_P + (row0 + 8) * PSS + col) = packf8(p2, p3);
                }
            }
        }
        bar_grp(1 + wr);   // P rows of this row-group visible to its 4 warps

        // ---- MMA2: O[32, 64-col slice] += P[32,128] @ H[128, 64-col slice]
        #pragma unroll
        for (int s2 = 0; s2 < 4; s2++) {
            uint32_t pa[2][4];
            #pragma unroll
            for (int mb = 0; mb < 2; mb++) {
                uint32_t addr = sb + OFF_P + (wr * 32 + mb * 16 + am) * PSS
                              + s2 * 32 + akc;
                ldsm_x4(pa[mb][0], pa[mb][1], pa[mb][2], pa[mb][3], addr);
            }
            #pragma unroll
            for (int jj = 0; jj < 4; jj++) {
                int nbase = wq * 64 + jj * 16;
                uint32_t addr = htbase + (nbase + hrow) * HTS + s2 * 32 + hkc;
                uint32_t b0, b1, b2, b3;
                ldsm_x4(b0, b1, b2, b3, addr);
                #pragma unroll
                for (int mb = 0; mb < 2; mb++) {
                    mma_fp8(oacc[mb * 8 + jj * 2],     pa[mb], b0, b1);
                    mma_fp8(oacc[mb * 8 + jj * 2 + 1], pa[mb], b2, b3);
                }
            }
        }
    }

    // ---- epilogue ----
    #pragma unroll
    for (int i = 0; i < 4; i++) {
        lsum[i] += __shfl_xor_sync(0xffffffffu, lsum[i], 1);
        lsum[i] += __shfl_xor_sync(0xffffffffu, lsum[i], 2);
    }
    float* Ls = (float*)(sm + OFF_L);
    __syncthreads();
    if (t == 0) {
        int r = wr * 32 + g;
        Ls[wq * 64 + r]      = lsum[0];
        Ls[wq * 64 + r + 8]  = lsum[1];
        Ls[wq * 64 + r + 16] = lsum[2];
        Ls[wq * 64 + r + 24] = lsum[3];
    }
    __syncthreads();

    #pragma unroll
    for (int mb = 0; mb < 2; mb++) {
        int row0 = wr * 32 + mb * 16 + g;
        float invA = 1.f / (Ls[row0] + Ls[64 + row0] + Ls[128 + row0] + Ls[192 + row0]);
        float invB = 1.f / (Ls[row0 + 8] + Ls[64 + row0 + 8] +
                            Ls[128 + row0 + 8] + Ls[192 + row0 + 8]);
        int grow0 = q0 + row0;
        #pragma unroll
        for (int jj = 0; jj < 4; jj++) {
            #pragma unroll
            for (int n8 = 0; n8 < 2; n8++) {
                int col = wq * 64 + jj * 16 + n8 * 8 + 2 * t;
                const float* oa = oacc[mb * 8 + jj * 2 + n8];
                float2 h0 = *(const float2*)(H + (size_t)grow0 * TT + col);
                float2 h1 = *(const float2*)(H + (size_t)(grow0 + 8) * TT + col);
                float2 o0, o1;
                o0.x = oa[0] * invA + h0.x;
                o0.y = oa[1] * invA + h0.y;
                o1.x = oa[2] * invB + h1.x;
                o1.y = oa[3] * invB + h1.y;
                *(float2*)(out + (size_t)grow0 * TT + col) = o0;
                *(float2*)(out + (size_t)(grow0 + 8) * TT + col) = o1;
            }
        }
    }
}

// ===========================================================================
extern "C" void kernel_launch(void* const* d_in, const int* in_sizes, int n_in,
                              void* d_out, int out_size) {
    const float* H  = (const float*)d_in[0];
    const float* Wq = (const float*)d_in[1];
    const float* bq = (const float*)d_in[2];
    const float* Wk = (const float*)d_in[3];
    const float* bk = (const float*)d_in[4];
    float* out = (float*)d_out;

    cudaFuncSetAttribute(attn12_kernel,
                         cudaFuncAttributeMaxDynamicSharedMemorySize, ATTN_SMEM);

    // 3 dummies: ncu -s 5 -c 1 then captures launch #5 = attn12_kernel
    dummy_kernel<<<1, 32>>>();
    dummy_kernel<<<1, 32>>>();
    dummy_kernel<<<1, 32>>>();
    qk_kernel<<<dim3(NN / 128, 2), 256>>>(H, Wq, bq, Wk, bk);
    ht_kernel<<<dim3(NN / 32, TT / 32), dim3(32, 8)>>>(H);
    attn12_kernel<<<NN / BM, 256, ATTN_SMEM>>>(H, out);
}

// round 13
// speedup vs baseline: 1.2324x; 1.2324x over previous
#include <cuda_runtime.h>
#include <cuda_bf16.h>
#include <cuda_fp16.h>
#include <cstdint>

#define NN 16384
#define DH 128
#define TT 256
#define QSCALE (0.08838834764831845f * 1.4426950408889634f)  // 1/sqrt(128) * log2(e)

#define BM 64
#define BN 128
#define NT (NN / BN)

// smem layout (bytes) — fp8 tiles (R11 layout, 1 CTA/SM)
#define KS 144
#define HTS 144
#define PSS 144
#define KBYTES (128 * KS)                   // 18432, 2 stages
#define HTBYTES (256 * HTS)                 // 36864, 2 stages
#define PBYTES (64 * PSS)                   // 9216
#define OFF_K 0
#define OFF_HT (2 * KBYTES)                 // 36864
#define OFF_P (OFF_HT + 2 * HTBYTES)        // 110592
#define OFF_L (OFF_P + PBYTES)              // 119808
#define ATTN_SMEM (OFF_L + 1024)            // 120832

// device-global scratch (allocation-guard safe)
__device__ uint8_t g_Qf[NN * DH];           // Q*QSCALE, e4m3
__device__ uint8_t g_Kf[NN * DH];           // K, e4m3
__device__ uint8_t g_HfT[(size_t)TT * NN];  // H transposed, e4m3

// ===========================================================================
// helpers
// ===========================================================================
__device__ __forceinline__ uint32_t smem_u32(const void* p) {
    uint32_t a;
    asm("{ .reg .u64 t; cvta.to.shared.u64 t, %1; cvt.u32.u64 %0, t; }"
        : "=r"(a) : "l"(p));
    return a;
}
__device__ __forceinline__ void ldsm_x4(uint32_t& r0, uint32_t& r1,
                                        uint32_t& r2, uint32_t& r3, uint32_t a) {
    asm volatile("ldmatrix.sync.aligned.m8n8.x4.shared.b16 {%0,%1,%2,%3}, [%4];"
                 : "=r"(r0), "=r"(r1), "=r"(r2), "=r"(r3) : "r"(a));
}
// fp8 e4m3 MMA, K=32, f16 accumulator (D/C = 2 x f16x2 regs)
__device__ __forceinline__ void mma_fp8h(uint32_t* d, const uint32_t* a,
                                         uint32_t b0, uint32_t b1) {
    asm volatile("mma.sync.aligned.m16n8k32.row.col.f16.e4m3.e4m3.f16 "
                 "{%0,%1},{%2,%3,%4,%5},{%6,%7},{%0,%1};"
                 : "+r"(d[0]), "+r"(d[1])
                 : "r"(a[0]), "r"(a[1]), "r"(a[2]), "r"(a[3]), "r"(b0), "r"(b1));
}
__device__ __forceinline__ void cp16(uint32_t dst, const void* src) {
    asm volatile("cp.async.cg.shared.global [%0], [%1], 16;"
                 :: "r"(dst), "l"(src) : "memory");
}
__device__ __forceinline__ void cp_commit() {
    asm volatile("cp.async.commit_group;" ::: "memory");
}
__device__ __forceinline__ void cp_wait0() {
    asm volatile("cp.async.wait_group 0;" ::: "memory");
}
__device__ __forceinline__ uint32_t ex2_h2(uint32_t x) {
    uint32_t y;
    asm("ex2.approx.f16x2 %0, %1;" : "=r"(y) : "r"(x));
    return y;
}
__device__ __forceinline__ uint32_t hadd2u(uint32_t a, uint32_t b) {
    uint32_t y;
    asm("add.f16x2 %0, %1, %2;" : "=r"(y) : "r"(a), "r"(b));
    return y;
}
__device__ __forceinline__ float2 h22f2(uint32_t h2) {
    __half2 h = *(__half2*)&h2;
    return __half22float2(h);
}
__device__ __forceinline__ uint16_t h2_to_e4m3x2(uint32_t h2) {
    uint16_t r;
    asm("cvt.rn.satfinite.e4m3x2.f16x2 %0, %1;" : "=h"(r) : "r"(h2));
    return r;
}
__device__ __forceinline__ uint16_t packf8(float lo, float hi) {
    uint16_t r;
    asm("cvt.rn.satfinite.e4m3x2.f32 %0, %1, %2;" : "=h"(r) : "f"(hi), "f"(lo));
    return r;
}
__device__ __forceinline__ void bar_grp(int id) {
    asm volatile("bar.sync %0, %1;" :: "r"(id), "r"(128) : "memory");
}

// ===========================================================================
// Kernel 1: Q = (H Wq + bq)*QSCALE -> e4m3 ; K = H Wk + bk -> e4m3 (2 CTA/SM)
// ===========================================================================
__global__ void __launch_bounds__(256, 2)
qk_kernel(const float* __restrict__ H,
          const float* __restrict__ Wq, const float* __restrict__ bq,
          const float* __restrict__ Wk, const float* __restrict__ bk) {
    __shared__ float HsT[32 * 129];
    __shared__ float Ws[32 * 128];

    const float* W = blockIdx.y ? Wk : Wq;
    const float* b = blockIdx.y ? bk : bq;
    uint8_t* outp  = blockIdx.y ? g_Kf : g_Qf;
    const float osc = blockIdx.y ? 1.0f : QSCALE;

    const int tid = threadIdx.x;
    const int ty = tid >> 4, tx = tid & 15;
    const int row0 = blockIdx.x * 128;

    float acc[8][8];
    #pragma unroll
    for (int i = 0; i < 8; i++)
        #pragma unroll
        for (int j = 0; j < 8; j++) acc[i][j] = 0.f;

    for (int kc = 0; kc < TT; kc += 32) {
        __syncthreads();
        #pragma unroll
        for (int idx = tid; idx < 128 * 32; idx += 256) {
            int r = idx >> 5, k = idx & 31;
            HsT[k * 129 + r] = H[(size_t)(row0 + r) * TT + kc + k];
        }
        #pragma unroll
        for (int idx = tid; idx < 32 * 128; idx += 256) {
            int k = idx >> 7, c = idx & 127;
            Ws[k * 128 + c] = W[(size_t)(kc + k) * DH + c];
        }
        __syncthreads();
        #pragma unroll 4
        for (int k = 0; k < 32; k++) {
            float h[8], w[8];
            #pragma unroll
            for (int i = 0; i < 8; i++) h[i] = HsT[k * 129 + ty * 8 + i];
            float4 w0 = *(const float4*)&Ws[k * 128 + tx * 8];
            float4 w1 = *(const float4*)&Ws[k * 128 + tx * 8 + 4];
            w[0]=w0.x; w[1]=w0.y; w[2]=w0.z; w[3]=w0.w;
            w[4]=w1.x; w[5]=w1.y; w[6]=w1.z; w[7]=w1.w;
            #pragma unroll
            for (int i = 0; i < 8; i++)
                #pragma unroll
                for (int j = 0; j < 8; j++)
                    acc[i][j] += h[i] * w[j];
        }
    }

    float bb[8];
    {
        float4 b0 = *(const float4*)&b[tx * 8];
        float4 b1 = *(const float4*)&b[tx * 8 + 4];
        bb[0]=b0.x; bb[1]=b0.y; bb[2]=b0.z; bb[3]=b0.w;
        bb[4]=b1.x; bb[5]=b1.y; bb[6]=b1.z; bb[7]=b1.w;
    }
    #pragma unroll
    for (int i = 0; i < 8; i++) {
        int r = row0 + ty * 8 + i;
        float v[8];
        #pragma unroll
        for (int j = 0; j < 8; j++) v[j] = (acc[i][j] + bb[j]) * osc;
        uint32_t lo = (uint32_t)packf8(v[0], v[1]) | ((uint32_t)packf8(v[2], v[3]) << 16);
        uint32_t hi = (uint32_t)packf8(v[4], v[5]) | ((uint32_t)packf8(v[6], v[7]) << 16);
        uint2 o; o.x = lo; o.y = hi;
        *(uint2*)&outp[(size_t)r * DH + tx * 8] = o;
    }
}

// ===========================================================================
// Kernel 2: H -> Hᵀ e4m3  (g_HfT[c][n])
// ===========================================================================
__global__ __launch_bounds__(256)
void ht_kernel(const float* __restrict__ H) {
    __shared__ float t[32][33];
    int bx = blockIdx.x * 32;   // n
    int by = blockIdx.y * 32;   // c
    int x = threadIdx.x, y = threadIdx.y;
    #pragma unroll
    for (int i = 0; i < 32; i += 8)
        t[y + i][x] = H[(size_t)(bx + y + i) * TT + by + x];
    __syncthreads();
    #pragma unroll
    for (int i = 0; i < 32; i += 8) {
        uint16_t r = packf8(t[x][y + i], 0.f);
        g_HfT[(size_t)(by + y + i) * NN + bx + x] = (uint8_t)(r & 0xff);
    }
}

// ===========================================================================
// Kernel 3: flash attention, all-fp8 mma with f16 accumulators.
// 8 warps: wr = wid>>2 (32 q-rows), wq = wid&3
// (MMA1: 32-key slice; MMA2: 64-col slice over full 128 keys).
// O: f16x2 accumulators merged into f32 master every 8 tiles.
// ===========================================================================
__device__ __forceinline__ void issue_tile(uint32_t sb, int tid, int k0, int stage) {
    {
        const uint8_t* src = g_Kf + (size_t)k0 * DH;
        uint32_t dstb = sb + OFF_K + stage * KBYTES;
        #pragma unroll
        for (int i = tid; i < 1024; i += 256) {
            int r = i >> 3, c = i & 7;
            cp16(dstb + r * KS + c * 16, src + r * 128 + c * 16);
        }
    }
    {
        uint32_t dstb = sb + OFF_HT + stage * HTBYTES;
        #pragma unroll
        for (int i = tid; i < 2048; i += 256) {
            int r = i >> 3, c = i & 7;
            cp16(dstb + r * HTS + c * 16, g_HfT + (size_t)r * NN + k0 + c * 16);
        }
    }
}

__global__ __launch_bounds__(256, 1)
void attn13_kernel(const float* __restrict__ H, float* __restrict__ out) {
    extern __shared__ char sm[];
    const uint32_t sb = smem_u32(sm);
    const int tid = threadIdx.x;
    const int wid = tid >> 5, lane = tid & 31;
    const int wr = wid >> 2, wq = wid & 3;
    const int g = lane >> 2, t = lane & 3;
    const int bl = lane >> 3, rl = lane & 7;
    const int q0 = blockIdx.x * BM;

    // prologue: tile 0 + Q (into P region)
    issue_tile(sb, tid, 0, 0);
    {
        const uint8_t* src = g_Qf + (size_t)q0 * DH;
        #pragma unroll
        for (int i = tid; i < 512; i += 256) {
            int r = i >> 3, c = i & 7;
            cp16(sb + OFF_P + r * PSS + c * 16, src + r * 128 + c * 16);
        }
    }
    cp_commit();
    cp_wait0();
    __syncthreads();

    // persistent Q A-frags: 2 m-blocks x 4 k32-steps
    uint32_t aq[2][4][4];
    #pragma unroll
    for (int mb = 0; mb < 2; mb++) {
        int m = wr * 32 + mb * 16 + rl + ((bl & 1) ? 8 : 0);
        #pragma unroll
        for (int s = 0; s < 4; s++) {
            uint32_t addr = sb + OFF_P + m * PSS + s * 32 + ((bl & 2) ? 16 : 0);
            ldsm_x4(aq[mb][s][0], aq[mb][s][1], aq[mb][s][2], aq[mb][s][3], addr);
        }
    }
    __syncthreads();   // Q reads done before P overwrites region

    float oacc[16][4];              // f32 master
    uint32_t o16[16][2];            // f16x2 per-8-tile accumulators
    #pragma unroll
    for (int i = 0; i < 16; i++) {
        o16[i][0] = 0; o16[i][1] = 0;
        #pragma unroll
        for (int j = 0; j < 4; j++) oacc[i][j] = 0.f;
    }
    float lsum[4] = {0.f, 0.f, 0.f, 0.f};
    const int diag_kt = q0 >> 7;

    const int nrowb = wq * 32 + rl + ((bl & 2) ? 8 : 0);   // MMA1 B key row
    const int kcb = (bl & 1) ? 16 : 0;
    const int am = rl + ((bl & 1) ? 8 : 0);                // MMA2 A row comp
    const int akc = (bl & 2) ? 16 : 0;
    const int hrow = rl + ((bl & 2) ? 8 : 0);              // MMA2 B col-row comp
    const int hkc = (bl & 1) ? 16 : 0;

    for (int kt = 0; kt < NT; kt++) {
        const int k0 = kt * BN;
        const int cur = kt & 1;

        cp_wait0();
        __syncthreads();

        if (kt + 1 < NT) {
            issue_tile(sb, tid, (kt + 1) * BN, cur ^ 1);
            cp_commit();
        }

        const uint32_t kbase  = sb + OFF_K + cur * KBYTES;
        const uint32_t htbase = sb + OFF_HT + cur * HTBYTES;

        // ---- MMA1 (f16 acc): S[32, 32-key slice] = Q @ K^T
        uint32_t sacc[2][4][2];
        #pragma unroll
        for (int mb = 0; mb < 2; mb++)
            #pragma unroll
            for (int jj = 0; jj < 4; jj++) { sacc[mb][jj][0] = 0; sacc[mb][jj][1] = 0; }

        #pragma unroll
        for (int s = 0; s < 4; s++) {
            #pragma unroll
            for (int nb = 0; nb < 2; nb++) {
                uint32_t addr = kbase + (nrowb + nb * 16) * KS + s * 32 + kcb;
                uint32_t b0, b1, b2, b3;
                ldsm_x4(b0, b1, b2, b3, addr);
                #pragma unroll
                for (int mb = 0; mb < 2; mb++) {
                    mma_fp8h(sacc[mb][2 * nb],     aq[mb][s], b0, b1);
                    mma_fp8h(sacc[mb][2 * nb + 1], aq[mb][s], b2, b3);
                }
            }
        }

        // ---- exp in f16x2 (scale folded), diag->1, row sums, publish P (e4m3)
        {
            const bool dt = (kt == diag_kt);
            #pragma unroll
            for (int mb = 0; mb < 2; mb++) {
                const int row0 = wr * 32 + mb * 16 + g;
                uint32_t hs0 = 0, hs1 = 0;   // f16x2 zero
                #pragma unroll
                for (int jj = 0; jj < 4; jj++) {
                    int col = wq * 32 + jj * 8 + 2 * t;
                    uint32_t r0 = sacc[mb][jj][0];   // row0: cols (col, col+1)
                    uint32_t r1 = sacc[mb][jj][1];   // row0+8
                    if (dt) {   // diagonal logit -> 0 (exp -> exactly 1)
                        int gcol = k0 + col;
                        int grow0 = q0 + row0, grow1 = grow0 + 8;
                        if (grow0 == gcol)     r0 &= 0xFFFF0000u;
                        if (grow0 == gcol + 1) r0 &= 0x0000FFFFu;
                        if (grow1 == gcol)     r1 &= 0xFFFF0000u;
                        if (grow1 == gcol + 1) r1 &= 0x0000FFFFu;
                    }
                    uint32_t p0 = ex2_h2(r0);
                    uint32_t p1 = ex2_h2(r1);
                    hs0 = hadd2u(hs0, p0);
                    hs1 = hadd2u(hs1, p1);
                    *(uint16_t*)(sm + OFF_P + row0 * PSS + col) = h2_to_e4m3x2(p0);
                    *(uint16_t*)(sm + OFF_P + (row0 + 8) * PSS + col) = h2_to_e4m3x2(p1);
                }
                float2 f0 = h22f2(hs0);
                float2 f1 = h22f2(hs1);
                lsum[2 * mb]     += f0.x + f0.y;
                lsum[2 * mb + 1] += f1.x + f1.y;
            }
        }
        bar_grp(1 + wr);   // P rows of this row-group visible to its 4 warps

        // ---- MMA2 (f16 acc): O16 += P[32,128] @ H[128, 64-col slice]
        #pragma unroll
        for (int s2 = 0; s2 < 4; s2++) {
            uint32_t pa[2][4];
            #pragma unroll
            for (int mb = 0; mb < 2; mb++) {
                uint32_t addr = sb + OFF_P + (wr * 32 + mb * 16 + am) * PSS
                              + s2 * 32 + akc;
                ldsm_x4(pa[mb][0], pa[mb][1], pa[mb][2], pa[mb][3], addr);
            }
            #pragma unroll
            for (int jj = 0; jj < 4; jj++) {
                int nbase = wq * 64 + jj * 16;
                uint32_t addr = htbase + (nbase + hrow) * HTS + s2 * 32 + hkc;
                uint32_t b0, b1, b2, b3;
                ldsm_x4(b0, b1, b2, b3, addr);
                #pragma unroll
                for (int mb = 0; mb < 2; mb++) {
                    mma_fp8h(o16[mb * 8 + jj * 2],     pa[mb], b0, b1);
                    mma_fp8h(o16[mb * 8 + jj * 2 + 1], pa[mb], b2, b3);
                }
            }
        }

        // ---- merge f16 partials into f32 master every 8 tiles
        if ((kt & 7) == 7) {
            #pragma unroll
            for (int i = 0; i < 16; i++) {
                float2 a = h22f2(o16[i][0]);
                float2 b = h22f2(o16[i][1]);
                oacc[i][0] += a.x; oacc[i][1] += a.y;
                oacc[i][2] += b.x; oacc[i][3] += b.y;
                o16[i][0] = 0; o16[i][1] = 0;
            }
        }
    }

    // ---- epilogue ----
    #pragma unroll
    for (int i = 0; i < 4; i++) {
        lsum[i] += __shfl_xor_sync(0xffffffffu, lsum[i], 1);
        lsum[i] += __shfl_xor_sync(0xffffffffu, lsum[i], 2);
    }
    float* Ls = (float*)(sm + OFF_L);
    __syncthreads();
    if (t == 0) {
        int r = wr * 32 + g;
        Ls[wq * 64 + r]      = lsum[0];
        Ls[wq * 64 + r + 8]  = lsum[1];
        Ls[wq * 64 + r + 16] = lsum[2];
        Ls[wq * 64 + r + 24] = lsum[3];
    }
    __syncthreads();

    #pragma unroll
    for (int mb = 0; mb < 2; mb++) {
        int row0 = wr * 32 + mb * 16 + g;
        float invA = 1.f / (Ls[row0] + Ls[64 + row0] + Ls[128 + row0] + Ls[192 + row0]);
        float invB = 1.f / (Ls[row0 + 8] + Ls[64 + row0 + 8] +
                            Ls[128 + row0 + 8] + Ls[192 + row0 + 8]);
        int grow0 = q0 + row0;
        #pragma unroll
        for (int jj = 0; jj < 4; jj++) {
            #pragma unroll
            for (int n8 = 0; n8 < 2; n8++) {
                int col = wq * 64 + jj * 16 + n8 * 8 + 2 * t;
                const float* oa = oacc[mb * 8 + jj * 2 + n8];
                float2 h0 = *(const float2*)(H + (size_t)grow0 * TT + col);
                float2 h1 = *(const float2*)(H + (size_t)(grow0 + 8) * TT + col);
                float2 o0, o1;
                o0.x = oa[0] * invA + h0.x;
                o0.y = oa[1] * invA + h0.y;
                o1.x = oa[2] * invB + h1.x;
                o1.y = oa[3] * invB + h1.y;
                *(float2*)(out + (size_t)grow0 * TT + col) = o0;
                *(float2*)(out + (size_t)(grow0 + 8) * TT + col) = o1;
            }
        }
    }
}

// ===========================================================================
extern "C" void kernel_launch(void* const* d_in, const int* in_sizes, int n_in,
                              void* d_out, int out_size) {
    const float* H  = (const float*)d_in[0];
    const float* Wq = (const float*)d_in[1];
    const float* bq = (const float*)d_in[2];
    const float* Wk = (const float*)d_in[3];
    const float* bk = (const float*)d_in[4];
    float* out = (float*)d_out;

    cudaFuncSetAttribute(attn13_kernel,
                         cudaFuncAttributeMaxDynamicSharedMemorySize, ATTN_SMEM);

    qk_kernel<<<dim3(NN / 128, 2), 256>>>(H, Wq, bq, Wk, bk);
    ht_kernel<<<dim3(NN / 32, TT / 32), dim3(32, 8)>>>(H);
    attn13_kernel<<<NN / BM, 256, ATTN_SMEM>>>(H, out);
}

// round 14
// speedup vs baseline: 1.3115x; 1.0641x over previous
#include <cuda_runtime.h>
#include <cuda_bf16.h>
#include <cuda_fp16.h>
#include <cstdint>

#define NN 16384
#define DH 128
#define TT 256
#define QSCALE (0.08838834764831845f * 1.4426950408889634f)  // 1/sqrt(128) * log2(e)

#define BM 64
#define BN 128
#define NT (NN / BN)

// smem layout (bytes) — fp8 tiles, trimmed for 2 CTAs/SM
#define KS 144
#define HTS 144
#define PSS 144
#define KBYTES (128 * KS)                   // 18432, SINGLE buffer
#define HTBYTES (256 * HTS)                 // 36864, 2 stages
#define QBYTES (64 * PSS)                   // 9216
#define PBYTES (64 * PSS)                   // 9216
#define OFF_K 0
#define OFF_HT KBYTES                       // 18432
#define OFF_Q (OFF_HT + 2 * HTBYTES)        // 92160
#define OFF_P (OFF_Q + QBYTES)              // 101376
#define OFF_L (OFF_P + PBYTES)              // 110592
#define ATTN_SMEM (OFF_L + 1024)            // 111616  (x2 = 223232 <= 228KB/SM)

// device-global scratch (allocation-guard safe)
__device__ uint8_t g_Qf[NN * DH];           // Q*QSCALE, e4m3
__device__ uint8_t g_Kf[NN * DH];           // K, e4m3
__device__ uint8_t g_HfT[(size_t)TT * NN];  // H transposed, e4m3

// ===========================================================================
// helpers
// ===========================================================================
__device__ __forceinline__ uint32_t smem_u32(const void* p) {
    uint32_t a;
    asm("{ .reg .u64 t; cvta.to.shared.u64 t, %1; cvt.u32.u64 %0, t; }"
        : "=r"(a) : "l"(p));
    return a;
}
__device__ __forceinline__ void ldsm_x4(uint32_t& r0, uint32_t& r1,
                                        uint32_t& r2, uint32_t& r3, uint32_t a) {
    asm volatile("ldmatrix.sync.aligned.m8n8.x4.shared.b16 {%0,%1,%2,%3}, [%4];"
                 : "=r"(r0), "=r"(r1), "=r"(r2), "=r"(r3) : "r"(a));
}
// fp8 e4m3 MMA, K=32, f16 accumulator
__device__ __forceinline__ void mma_fp8h(uint32_t* d, const uint32_t* a,
                                         uint32_t b0, uint32_t b1) {
    asm volatile("mma.sync.aligned.m16n8k32.row.col.f16.e4m3.e4m3.f16 "
                 "{%0,%1},{%2,%3,%4,%5},{%6,%7},{%0,%1};"
                 : "+r"(d[0]), "+r"(d[1])
                 : "r"(a[0]), "r"(a[1]), "r"(a[2]), "r"(a[3]), "r"(b0), "r"(b1));
}
__device__ __forceinline__ void cp16(uint32_t dst, const void* src) {
    asm volatile("cp.async.cg.shared.global [%0], [%1], 16;"
                 :: "r"(dst), "l"(src) : "memory");
}
__device__ __forceinline__ void cp_commit() {
    asm volatile("cp.async.commit_group;" ::: "memory");
}
__device__ __forceinline__ void cp_wait0() {
    asm volatile("cp.async.wait_group 0;" ::: "memory");
}
__device__ __forceinline__ uint32_t ex2_h2(uint32_t x) {
    uint32_t y;
    asm("ex2.approx.f16x2 %0, %1;" : "=r"(y) : "r"(x));
    return y;
}
__device__ __forceinline__ uint32_t hadd2u(uint32_t a, uint32_t b) {
    uint32_t y;
    asm("add.f16x2 %0, %1, %2;" : "=r"(y) : "r"(a), "r"(b));
    return y;
}
__device__ __forceinline__ float2 h22f2(uint32_t h2) {
    __half2 h = *(__half2*)&h2;
    return __half22float2(h);
}
__device__ __forceinline__ uint16_t h2_to_e4m3x2(uint32_t h2) {
    uint16_t r;
    asm("cvt.rn.satfinite.e4m3x2.f16x2 %0, %1;" : "=h"(r) : "r"(h2));
    return r;
}
__device__ __forceinline__ uint16_t packf8(float lo, float hi) {
    uint16_t r;
    asm("cvt.rn.satfinite.e4m3x2.f32 %0, %1, %2;" : "=h"(r) : "f"(hi), "f"(lo));
    return r;
}
__device__ __forceinline__ void bar_grp(int id) {
    asm volatile("bar.sync %0, %1;" :: "r"(id), "r"(128) : "memory");
}

// ===========================================================================
// Kernel 1: Q = (H Wq + bq)*QSCALE -> e4m3 ; K = H Wk + bk -> e4m3 (2 CTA/SM)
// ===========================================================================
__global__ void __launch_bounds__(256, 2)
qk_kernel(const float* __restrict__ H,
          const float* __restrict__ Wq, const float* __restrict__ bq,
          const float* __restrict__ Wk, const float* __restrict__ bk) {
    __shared__ float HsT[32 * 129];
    __shared__ float Ws[32 * 128];

    const float* W = blockIdx.y ? Wk : Wq;
    const float* b = blockIdx.y ? bk : bq;
    uint8_t* outp  = blockIdx.y ? g_Kf : g_Qf;
    const float osc = blockIdx.y ? 1.0f : QSCALE;

    const int tid = threadIdx.x;
    const int ty = tid >> 4, tx = tid & 15;
    const int row0 = blockIdx.x * 128;

    float acc[8][8];
    #pragma unroll
    for (int i = 0; i < 8; i++)
        #pragma unroll
        for (int j = 0; j < 8; j++) acc[i][j] = 0.f;

    for (int kc = 0; kc < TT; kc += 32) {
        __syncthreads();
        #pragma unroll
        for (int idx = tid; idx < 128 * 32; idx += 256) {
            int r = idx >> 5, k = idx & 31;
            HsT[k * 129 + r] = H[(size_t)(row0 + r) * TT + kc + k];
        }
        #pragma unroll
        for (int idx = tid; idx < 32 * 128; idx += 256) {
            int k = idx >> 7, c = idx & 127;
            Ws[k * 128 + c] = W[(size_t)(kc + k) * DH + c];
        }
        __syncthreads();
        #pragma unroll 4
        for (int k = 0; k < 32; k++) {
            float h[8], w[8];
            #pragma unroll
            for (int i = 0; i < 8; i++) h[i] = HsT[k * 129 + ty * 8 + i];
            float4 w0 = *(const float4*)&Ws[k * 128 + tx * 8];
            float4 w1 = *(const float4*)&Ws[k * 128 + tx * 8 + 4];
            w[0]=w0.x; w[1]=w0.y; w[2]=w0.z; w[3]=w0.w;
            w[4]=w1.x; w[5]=w1.y; w[6]=w1.z; w[7]=w1.w;
            #pragma unroll
            for (int i = 0; i < 8; i++)
                #pragma unroll
                for (int j = 0; j < 8; j++)
                    acc[i][j] += h[i] * w[j];
        }
    }

    float bb[8];
    {
        float4 b0 = *(const float4*)&b[tx * 8];
        float4 b1 = *(const float4*)&b[tx * 8 + 4];
        bb[0]=b0.x; bb[1]=b0.y; bb[2]=b0.z; bb[3]=b0.w;
        bb[4]=b1.x; bb[5]=b1.y; bb[6]=b1.z; bb[7]=b1.w;
    }
    #pragma unroll
    for (int i = 0; i < 8; i++) {
        int r = row0 + ty * 8 + i;
        float v[8];
        #pragma unroll
        for (int j = 0; j < 8; j++) v[j] = (acc[i][j] + bb[j]) * osc;
        uint32_t lo = (uint32_t)packf8(v[0], v[1]) | ((uint32_t)packf8(v[2], v[3]) << 16);
        uint32_t hi = (uint32_t)packf8(v[4], v[5]) | ((uint32_t)packf8(v[6], v[7]) << 16);
        uint2 o; o.x = lo; o.y = hi;
        *(uint2*)&outp[(size_t)r * DH + tx * 8] = o;
    }
}

// ===========================================================================
// Kernel 2: H -> Hᵀ e4m3  (g_HfT[c][n])
// ===========================================================================
__global__ __launch_bounds__(256)
void ht_kernel(const float* __restrict__ H) {
    __shared__ float t[32][33];
    int bx = blockIdx.x * 32;   // n
    int by = blockIdx.y * 32;   // c
    int x = threadIdx.x, y = threadIdx.y;
    #pragma unroll
    for (int i = 0; i < 32; i += 8)
        t[y + i][x] = H[(size_t)(bx + y + i) * TT + by + x];
    __syncthreads();
    #pragma unroll
    for (int i = 0; i < 32; i += 8) {
        uint16_t r = packf8(t[x][y + i], 0.f);
        g_HfT[(size_t)(by + y + i) * NN + bx + x] = (uint8_t)(r & 0xff);
    }
}

// ===========================================================================
// Kernel 3: flash attention, all-fp8 mma, f16 accumulators, 2 CTAs/SM.
// 8 warps: wr = wid>>2 (32 q-rows), wq = wid&3.
// Q frags reloaded from smem each tile (saves 32 regs for 2-CTA residency).
// O: f16x2 chunk accumulators merged into f16x2 master every 8 tiles.
// ===========================================================================
__device__ __forceinline__ void issue_k(uint32_t sb, int tid, int k0) {
    const uint8_t* src = g_Kf + (size_t)k0 * DH;
    #pragma unroll
    for (int i = tid; i < 1024; i += 256) {
        int r = i >> 3, c = i & 7;
        cp16(sb + OFF_K + r * KS + c * 16, src + r * 128 + c * 16);
    }
}
__device__ __forceinline__ void issue_ht(uint32_t sb, int tid, int k0, int stage) {
    uint32_t dstb = sb + OFF_HT + stage * HTBYTES;
    #pragma unroll
    for (int i = tid; i < 2048; i += 256) {
        int r = i >> 3, c = i & 7;
        cp16(dstb + r * HTS + c * 16, g_HfT + (size_t)r * NN + k0 + c * 16);
    }
}

__global__ void __launch_bounds__(256, 2)
attn14_kernel(const float* __restrict__ H, float* __restrict__ out) {
    extern __shared__ char sm[];
    const uint32_t sb = smem_u32(sm);
    const int tid = threadIdx.x;
    const int wid = tid >> 5, lane = tid & 31;
    const int wr = wid >> 2, wq = wid & 3;
    const int g = lane >> 2, t = lane & 3;
    const int bl = lane >> 3, rl = lane & 7;
    const int q0 = blockIdx.x * BM;

    // prologue: K(0), HT(0), Q in one cp.async group
    issue_k(sb, tid, 0);
    issue_ht(sb, tid, 0, 0);
    {
        const uint8_t* src = g_Qf + (size_t)q0 * DH;
        #pragma unroll
        for (int i = tid; i < 512; i += 256) {
            int r = i >> 3, c = i & 7;
            cp16(sb + OFF_Q + r * PSS + c * 16, src + r * 128 + c * 16);
        }
    }
    cp_commit();

    uint32_t o16[16][2];            // f16x2 per-8-tile chunk
    uint32_t om[16][2];             // f16x2 master
    #pragma unroll
    for (int i = 0; i < 16; i++) {
        o16[i][0] = 0; o16[i][1] = 0;
        om[i][0] = 0;  om[i][1] = 0;
    }
    float lsum[4] = {0.f, 0.f, 0.f, 0.f};
    const int diag_kt = q0 >> 7;

    // lane-constant address components
    const int aqm0 = wr * 32 + rl + ((bl & 1) ? 8 : 0);    // Q A-frag row, mb0
    const int aqkc = (bl & 2) ? 16 : 0;
    const int nrowb = wq * 32 + rl + ((bl & 2) ? 8 : 0);   // MMA1 B key row
    const int kcb = (bl & 1) ? 16 : 0;
    const int am = rl + ((bl & 1) ? 8 : 0);                // MMA2 A (P) row comp
    const int akc = (bl & 2) ? 16 : 0;
    const int hrow = rl + ((bl & 2) ? 8 : 0);              // MMA2 B (HT) row comp
    const int hkc = (bl & 1) ? 16 : 0;

    cp_wait0();
    __syncthreads();

    for (int kt = 0; kt < NT; kt++) {
        const int k0 = kt * BN;
        const int cur = kt & 1;
        const uint32_t htbase = sb + OFF_HT + cur * HTBYTES;

        // ---- MMA1 (f16 acc): S[32, 32-key slice] = Q @ K^T, aq from smem
        uint32_t sacc[2][4][2];
        #pragma unroll
        for (int mb = 0; mb < 2; mb++)
            #pragma unroll
            for (int jj = 0; jj < 4; jj++) { sacc[mb][jj][0] = 0; sacc[mb][jj][1] = 0; }

        #pragma unroll
        for (int s = 0; s < 4; s++) {
            uint32_t aq0[4], aq1[4];
            ldsm_x4(aq0[0], aq0[1], aq0[2], aq0[3],
                    sb + OFF_Q + aqm0 * PSS + s * 32 + aqkc);
            ldsm_x4(aq1[0], aq1[1], aq1[2], aq1[3],
                    sb + OFF_Q + (aqm0 + 16) * PSS + s * 32 + aqkc);
            #pragma unroll
            for (int nb = 0; nb < 2; nb++) {
                uint32_t addr = sb + OFF_K + (nrowb + nb * 16) * KS + s * 32 + kcb;
                uint32_t b0, b1, b2, b3;
                ldsm_x4(b0, b1, b2, b3, addr);
                mma_fp8h(sacc[0][2 * nb],     aq0, b0, b1);
                mma_fp8h(sacc[0][2 * nb + 1], aq0, b2, b3);
                mma_fp8h(sacc[1][2 * nb],     aq1, b0, b1);
                mma_fp8h(sacc[1][2 * nb + 1], aq1, b2, b3);
            }
        }
        __syncthreads();   // all warps done reading K (single buffer)

        if (kt + 1 < NT) {     // prefetch next K + HT (other stage, free since kt-1)
            issue_k(sb, tid, (kt + 1) * BN);
            issue_ht(sb, tid, (kt + 1) * BN, cur ^ 1);
            cp_commit();
        }

        // ---- exp in f16x2, diag->1, row sums, publish P (e4m3)
        {
            const bool dt = (kt == diag_kt);
            #pragma unroll
            for (int mb = 0; mb < 2; mb++) {
                const int row0 = wr * 32 + mb * 16 + g;
                uint32_t hs0 = 0, hs1 = 0;
                #pragma unroll
                for (int jj = 0; jj < 4; jj++) {
                    int col = wq * 32 + jj * 8 + 2 * t;
                    uint32_t r0 = sacc[mb][jj][0];
                    uint32_t r1 = sacc[mb][jj][1];
                    if (dt) {   // diagonal logit -> 0 (exp -> exactly 1)
                        int gcol = k0 + col;
                        int grow0 = q0 + row0, grow1 = grow0 + 8;
                        if (grow0 == gcol)     r0 &= 0xFFFF0000u;
                        if (grow0 == gcol + 1) r0 &= 0x0000FFFFu;
                        if (grow1 == gcol)     r1 &= 0xFFFF0000u;
                        if (grow1 == gcol + 1) r1 &= 0x0000FFFFu;
                    }
                    uint32_t p0 = ex2_h2(r0);
                    uint32_t p1 = ex2_h2(r1);
                    hs0 = hadd2u(hs0, p0);
                    hs1 = hadd2u(hs1, p1);
                    *(uint16_t*)(sm + OFF_P + row0 * PSS + col) = h2_to_e4m3x2(p0);
                    *(uint16_t*)(sm + OFF_P + (row0 + 8) * PSS + col) = h2_to_e4m3x2(p1);
                }
                float2 f0 = h22f2(hs0);
                float2 f1 = h22f2(hs1);
                lsum[2 * mb]     += f0.x + f0.y;
                lsum[2 * mb + 1] += f1.x + f1.y;
            }
        }
        bar_grp(1 + wr);   // P rows of this row-group visible to its 4 warps

        // ---- MMA2 (f16 acc): o16 += P[32,128] @ H[128, 64-col slice]
        #pragma unroll
        for (int s2 = 0; s2 < 4; s2++) {
            uint32_t pa[2][4];
            #pragma unroll
            for (int mb = 0; mb < 2; mb++) {
                uint32_t addr = sb + OFF_P + (wr * 32 + mb * 16 + am) * PSS
                              + s2 * 32 + akc;
                ldsm_x4(pa[mb][0], pa[mb][1], pa[mb][2], pa[mb][3], addr);
            }
            #pragma unroll
            for (int jj = 0; jj < 4; jj++) {
                int nbase = wq * 64 + jj * 16;
                uint32_t addr = htbase + (nbase + hrow) * HTS + s2 * 32 + hkc;
                uint32_t b0, b1, b2, b3;
                ldsm_x4(b0, b1, b2, b3, addr);
                #pragma unroll
                for (int mb = 0; mb < 2; mb++) {
                    mma_fp8h(o16[mb * 8 + jj * 2],     pa[mb], b0, b1);
                    mma_fp8h(o16[mb * 8 + jj * 2 + 1], pa[mb], b2, b3);
                }
            }
        }

        // ---- merge chunk into f16x2 master every 8 tiles
        if ((kt & 7) == 7) {
            #pragma unroll
            for (int i = 0; i < 16; i++) {
                om[i][0] = hadd2u(om[i][0], o16[i][0]);
                om[i][1] = hadd2u(om[i][1], o16[i][1]);
                o16[i][0] = 0; o16[i][1] = 0;
            }
        }

        // loop-top barrier for next iteration: tile kt+1 ready + all MMA2 done
        cp_wait0();
        __syncthreads();
    }

    // ---- epilogue ----
    #pragma unroll
    for (int i = 0; i < 4; i++) {
        lsum[i] += __shfl_xor_sync(0xffffffffu, lsum[i], 1);
        lsum[i] += __shfl_xor_sync(0xffffffffu, lsum[i], 2);
    }
    float* Ls = (float*)(sm + OFF_L);
    if (t == 0) {
        int r = wr * 32 + g;
        Ls[wq * 64 + r]      = lsum[0];
        Ls[wq * 64 + r + 8]  = lsum[1];
        Ls[wq * 64 + r + 16] = lsum[2];
        Ls[wq * 64 + r + 24] = lsum[3];
    }
    __syncthreads();

    #pragma unroll
    for (int mb = 0; mb < 2; mb++) {
        int row0 = wr * 32 + mb * 16 + g;
        float invA = 1.f / (Ls[row0] + Ls[64 + row0] + Ls[128 + row0] + Ls[192 + row0]);
        float invB = 1.f / (Ls[row0 + 8] + Ls[64 + row0 + 8] +
                            Ls[128 + row0 + 8] + Ls[192 + row0 + 8]);
        int grow0 = q0 + row0;
        #pragma unroll
        for (int jj = 0; jj < 4; jj++) {
            #pragma unroll
            for (int n8 = 0; n8 < 2; n8++) {
                int col = wq * 64 + jj * 16 + n8 * 8 + 2 * t;
                int idx = mb * 8 + jj * 2 + n8;
                float2 a = h22f2(om[idx][0]);
                float2 b = h22f2(om[idx][1]);
                float2 h0 = *(const float2*)(H + (size_t)grow0 * TT + col);
                float2 h1 = *(const float2*)(H + (size_t)(grow0 + 8) * TT + col);
                float2 o0, o1;
                o0.x = a.x * invA + h0.x;
                o0.y = a.y * invA + h0.y;
                o1.x = b.x * invB + h1.x;
                o1.y = b.y * invB + h1.y;
                *(float2*)(out + (size_t)grow0 * TT + col) = o0;
                *(float2*)(out + (size_t)(grow0 + 8) * TT + col) = o1;
            }
        }
    }
}

// ===========================================================================
extern "C" void kernel_launch(void* const* d_in, const int* in_sizes, int n_in,
                              void* d_out, int out_size) {
    const float* H  = (const float*)d_in[0];
    const float* Wq = (const float*)d_in[1];
    const float* bq = (const float*)d_in[2];
    const float* Wk = (const float*)d_in[3];
    const float* bk = (const float*)d_in[4];
    float* out = (float*)d_out;

    cudaFuncSetAttribute(attn14_kernel,
                         cudaFuncAttributeMaxDynamicSharedMemorySize, ATTN_SMEM);

    qk_kernel<<<dim3(NN / 128, 2), 256>>>(H, Wq, bq, Wk, bk);
    ht_kernel<<<dim3(NN / 32, TT / 32), dim3(32, 8)>>>(H);
    attn14_kernel<<<NN / BM, 256, ATTN_SMEM>>>(H, out);
}

// round 15
// speedup vs baseline: 1.3823x; 1.0540x over previous
#include <cuda_runtime.h>
#include <cuda_bf16.h>
#include <cuda_fp16.h>
#include <cstdint>

#define NN 16384
#define DH 128
#define TT 256
#define QSCALE (0.08838834764831845f * 1.4426950408889634f)  // 1/sqrt(128) * log2(e)

#define BM 64
#define BN 128
#define NT (NN / BN)

// ---- attn smem layout (bytes) — fp8 tiles, 2 CTAs/SM ----
#define KS 144
#define HTS 144
#define PSS 144
#define KBYTES (128 * KS)                   // 18432, SINGLE buffer
#define HTBYTES (256 * HTS)                 // 36864, 2 stages
#define QBYTES (64 * PSS)                   // 9216
#define PBYTES (64 * PSS)                   // 9216
#define OFF_K 0
#define OFF_HT KBYTES                       // 18432
#define OFF_Q (OFF_HT + 2 * HTBYTES)        // 92160
#define OFF_P (OFF_Q + QBYTES)              // 101376
#define OFF_L (OFF_P + PBYTES)              // 110592
#define ATTN_SMEM (OFF_L + 1024)            // 111616  (x2 <= 228KB/SM)

// ---- qk (bf16 tensor GEMM) smem layout ----
#define QK_HS 528                           // H row: 256 bf16 + 8 pad
#define QK_WS 272                           // W row: 128 bf16 + 8 pad
#define QK_OFF_W (128 * QK_HS)              // 67584
#define QK_SMEM (QK_OFF_W + 256 * QK_WS)    // 137216

// device-global scratch (allocation-guard safe)
__device__ uint8_t g_Qf[NN * DH];           // Q*QSCALE, e4m3
__device__ uint8_t g_Kf[NN * DH];           // K, e4m3
__device__ uint8_t g_HfT[(size_t)TT * NN];  // H transposed, e4m3

// ===========================================================================
// helpers
// ===========================================================================
__device__ __forceinline__ uint32_t smem_u32(const void* p) {
    uint32_t a;
    asm("{ .reg .u64 t; cvta.to.shared.u64 t, %1; cvt.u32.u64 %0, t; }"
        : "=r"(a) : "l"(p));
    return a;
}
__device__ __forceinline__ void ldsm_x4(uint32_t& r0, uint32_t& r1,
                                        uint32_t& r2, uint32_t& r3, uint32_t a) {
    asm volatile("ldmatrix.sync.aligned.m8n8.x4.shared.b16 {%0,%1,%2,%3}, [%4];"
                 : "=r"(r0), "=r"(r1), "=r"(r2), "=r"(r3) : "r"(a));
}
__device__ __forceinline__ void ldsm_x4_t(uint32_t& r0, uint32_t& r1,
                                          uint32_t& r2, uint32_t& r3, uint32_t a) {
    asm volatile("ldmatrix.sync.aligned.m8n8.x4.trans.shared.b16 {%0,%1,%2,%3}, [%4];"
                 : "=r"(r0), "=r"(r1), "=r"(r2), "=r"(r3) : "r"(a));
}
// bf16 MMA k16, f32 acc (for qk projection)
__device__ __forceinline__ void mma16816(float* d, const uint32_t* a,
                                         uint32_t b0, uint32_t b1) {
    asm volatile("mma.sync.aligned.m16n8k16.row.col.f32.bf16.bf16.f32 "
                 "{%0,%1,%2,%3},{%4,%5,%6,%7},{%8,%9},{%0,%1,%2,%3};"
                 : "+f"(d[0]), "+f"(d[1]), "+f"(d[2]), "+f"(d[3])
                 : "r"(a[0]), "r"(a[1]), "r"(a[2]), "r"(a[3]), "r"(b0), "r"(b1));
}
// fp8 e4m3 MMA, K=32, f16 accumulator
__device__ __forceinline__ void mma_fp8h(uint32_t* d, const uint32_t* a,
                                         uint32_t b0, uint32_t b1) {
    asm volatile("mma.sync.aligned.m16n8k32.row.col.f16.e4m3.e4m3.f16 "
                 "{%0,%1},{%2,%3,%4,%5},{%6,%7},{%0,%1};"
                 : "+r"(d[0]), "+r"(d[1])
                 : "r"(a[0]), "r"(a[1]), "r"(a[2]), "r"(a[3]), "r"(b0), "r"(b1));
}
__device__ __forceinline__ void cp16(uint32_t dst, const void* src) {
    asm volatile("cp.async.cg.shared.global [%0], [%1], 16;"
                 :: "r"(dst), "l"(src) : "memory");
}
__device__ __forceinline__ void cp_commit() {
    asm volatile("cp.async.commit_group;" ::: "memory");
}
__device__ __forceinline__ void cp_wait0() {
    asm volatile("cp.async.wait_group 0;" ::: "memory");
}
__device__ __forceinline__ uint32_t ex2_h2(uint32_t x) {
    uint32_t y;
    asm("ex2.approx.f16x2 %0, %1;" : "=r"(y) : "r"(x));
    return y;
}
__device__ __forceinline__ uint32_t hadd2u(uint32_t a, uint32_t b) {
    uint32_t y;
    asm("add.f16x2 %0, %1, %2;" : "=r"(y) : "r"(a), "r"(b));
    return y;
}
__device__ __forceinline__ float2 h22f2(uint32_t h2) {
    __half2 h = *(__half2*)&h2;
    return __half22float2(h);
}
__device__ __forceinline__ uint16_t h2_to_e4m3x2(uint32_t h2) {
    uint16_t r;
    asm("cvt.rn.satfinite.e4m3x2.f16x2 %0, %1;" : "=h"(r) : "r"(h2));
    return r;
}
__device__ __forceinline__ uint16_t packf8(float lo, float hi) {
    uint16_t r;
    asm("cvt.rn.satfinite.e4m3x2.f32 %0, %1, %2;" : "=h"(r) : "f"(hi), "f"(lo));
    return r;
}
__device__ __forceinline__ void bar_grp(int id) {
    asm volatile("bar.sync %0, %1;" :: "r"(id), "r"(128) : "memory");
}

// ===========================================================================
// Kernel 1: Q = (H Wq + bq)*QSCALE -> e4m3 ; K = H Wk + bk -> e4m3
// bf16 tensor-core GEMM. 128x128 tile/CTA, K=256 (16 k16-steps).
// Warp (wr = wid>>1: 32 rows) x (wc = wid&1: 64 cols).
// ===========================================================================
__global__ __launch_bounds__(256)
void qk2_kernel(const float* __restrict__ H,
                const float* __restrict__ Wq, const float* __restrict__ bq,
                const float* __restrict__ Wk, const float* __restrict__ bk) {
    extern __shared__ char qsm[];
    const uint32_t sbq = smem_u32(qsm);

    const float* W = blockIdx.y ? Wk : Wq;
    const float* b = blockIdx.y ? bk : bq;
    uint8_t* outp  = blockIdx.y ? g_Kf : g_Qf;
    const float osc = blockIdx.y ? 1.0f : QSCALE;

    const int tid = threadIdx.x;
    const int wid = tid >> 5, lane = tid & 31;
    const int wr = wid >> 1, wc = wid & 1;
    const int g = lane >> 2, t = lane & 3;
    const int bl = lane >> 3, rl = lane & 7;
    const int row0 = blockIdx.x * 128;

    // load H tile (128 x 256 fp32 -> bf16)
    for (int i = tid; i < 128 * 64; i += 256) {
        int r = i >> 6, c4 = i & 63;
        float4 v = *(const float4*)(H + (size_t)(row0 + r) * TT + c4 * 4);
        __nv_bfloat162 a = __floats2bfloat162_rn(v.x, v.y);
        __nv_bfloat162 bb = __floats2bfloat162_rn(v.z, v.w);
        uint2 o; o.x = *(uint32_t*)&a; o.y = *(uint32_t*)&bb;
        *(uint2*)(qsm + r * QK_HS + c4 * 8) = o;
    }
    // load W (256 x 128 fp32 -> bf16)
    for (int i = tid; i < 256 * 32; i += 256) {
        int r = i >> 5, c4 = i & 31;
        float4 v = *(const float4*)(W + (size_t)r * DH + c4 * 4);
        __nv_bfloat162 a = __floats2bfloat162_rn(v.x, v.y);
        __nv_bfloat162 bb = __floats2bfloat162_rn(v.z, v.w);
        uint2 o; o.x = *(uint32_t*)&a; o.y = *(uint32_t*)&bb;
        *(uint2*)(qsm + QK_OFF_W + r * QK_WS + c4 * 8) = o;
    }
    __syncthreads();

    const int m0 = wr * 32;
    const int arow = m0 + rl + ((bl & 1) ? 8 : 0);
    const int akc = (bl & 2) ? 16 : 0;
    const int bkr = rl + ((bl & 1) ? 8 : 0);
    const int bn = (bl & 2) ? 8 : 0;

    float acc[16][4];
    #pragma unroll
    for (int i = 0; i < 16; i++)
        #pragma unroll
        for (int j = 0; j < 4; j++) acc[i][j] = 0.f;

    #pragma unroll
    for (int ks = 0; ks < 16; ks++) {
        uint32_t a0[4], a1[4];
        ldsm_x4(a0[0], a0[1], a0[2], a0[3],
                sbq + arow * QK_HS + ks * 32 + akc);
        ldsm_x4(a1[0], a1[1], a1[2], a1[3],
                sbq + (arow + 16) * QK_HS + ks * 32 + akc);
        #pragma unroll
        for (int jj = 0; jj < 4; jj++) {
            uint32_t addr = sbq + QK_OFF_W + (ks * 16 + bkr) * QK_WS
                          + (wc * 64 + jj * 16 + bn) * 2;
            uint32_t b0, b1, b2, b3;
            ldsm_x4_t(b0, b1, b2, b3, addr);
            mma16816(acc[jj * 2],     a0, b0, b1);
            mma16816(acc[jj * 2 + 1], a0, b2, b3);
            mma16816(acc[8 + jj * 2],     a1, b0, b1);
            mma16816(acc[8 + jj * 2 + 1], a1, b2, b3);
        }
    }

    // epilogue: +bias, *scale, -> e4m3
    #pragma unroll
    for (int mb = 0; mb < 2; mb++) {
        int r0 = row0 + m0 + mb * 16 + g;
        #pragma unroll
        for (int jj = 0; jj < 4; jj++) {
            #pragma unroll
            for (int n8 = 0; n8 < 2; n8++) {
                int col = wc * 64 + jj * 16 + n8 * 8 + 2 * t;
                const float* oa = acc[mb * 8 + jj * 2 + n8];
                float b0v = b[col], b1v = b[col + 1];
                *(uint16_t*)&outp[(size_t)r0 * DH + col] =
                    packf8((oa[0] + b0v) * osc, (oa[1] + b1v) * osc);
                *(uint16_t*)&outp[(size_t)(r0 + 8) * DH + col] =
                    packf8((oa[2] + b0v) * osc, (oa[3] + b1v) * osc);
            }
        }
    }
}

// ===========================================================================
// Kernel 2: H -> Hᵀ e4m3  (g_HfT[c][n])
// ===========================================================================
__global__ __launch_bounds__(256)
void ht_kernel(const float* __restrict__ H) {
    __shared__ float tt[32][33];
    int bx = blockIdx.x * 32;   // n
    int by = blockIdx.y * 32;   // c
    int x = threadIdx.x, y = threadIdx.y;
    #pragma unroll
    for (int i = 0; i < 32; i += 8)
        tt[y + i][x] = H[(size_t)(bx + y + i) * TT + by + x];
    __syncthreads();
    #pragma unroll
    for (int i = 0; i < 32; i += 8) {
        uint16_t r = packf8(tt[x][y + i], 0.f);
        g_HfT[(size_t)(by + y + i) * NN + bx + x] = (uint8_t)(r & 0xff);
    }
}

// ===========================================================================
// Kernel 3: flash attention, all-fp8 mma, f16 accumulators, 2 CTAs/SM.
// (unchanged from round 14)
// ===========================================================================
__device__ __forceinline__ void issue_k(uint32_t sb, int tid, int k0) {
    const uint8_t* src = g_Kf + (size_t)k0 * DH;
    #pragma unroll
    for (int i = tid; i < 1024; i += 256) {
        int r = i >> 3, c = i & 7;
        cp16(sb + OFF_K + r * KS + c * 16, src + r * 128 + c * 16);
    }
}
__device__ __forceinline__ void issue_ht(uint32_t sb, int tid, int k0, int stage) {
    uint32_t dstb = sb + OFF_HT + stage * HTBYTES;
    #pragma unroll
    for (int i = tid; i < 2048; i += 256) {
        int r = i >> 3, c = i & 7;
        cp16(dstb + r * HTS + c * 16, g_HfT + (size_t)r * NN + k0 + c * 16);
    }
}

__global__ void __launch_bounds__(256, 2)
attn15_kernel(const float* __restrict__ H, float* __restrict__ out) {
    extern __shared__ char sm[];
    const uint32_t sb = smem_u32(sm);
    const int tid = threadIdx.x;
    const int wid = tid >> 5, lane = tid & 31;
    const int wr = wid >> 2, wq = wid & 3;
    const int g = lane >> 2, t = lane & 3;
    const int bl = lane >> 3, rl = lane & 7;
    const int q0 = blockIdx.x * BM;

    issue_k(sb, tid, 0);
    issue_ht(sb, tid, 0, 0);
    {
        const uint8_t* src = g_Qf + (size_t)q0 * DH;
        #pragma unroll
        for (int i = tid; i < 512; i += 256) {
            int r = i >> 3, c = i & 7;
            cp16(sb + OFF_Q + r * PSS + c * 16, src + r * 128 + c * 16);
        }
    }
    cp_commit();

    uint32_t o16[16][2];
    uint32_t om[16][2];
    #pragma unroll
    for (int i = 0; i < 16; i++) {
        o16[i][0] = 0; o16[i][1] = 0;
        om[i][0] = 0;  om[i][1] = 0;
    }
    float lsum[4] = {0.f, 0.f, 0.f, 0.f};
    const int diag_kt = q0 >> 7;

    const int aqm0 = wr * 32 + rl + ((bl & 1) ? 8 : 0);
    const int aqkc = (bl & 2) ? 16 : 0;
    const int nrowb = wq * 32 + rl + ((bl & 2) ? 8 : 0);
    const int kcb = (bl & 1) ? 16 : 0;
    const int am = rl + ((bl & 1) ? 8 : 0);
    const int akc = (bl & 2) ? 16 : 0;
    const int hrow = rl + ((bl & 2) ? 8 : 0);
    const int hkc = (bl & 1) ? 16 : 0;

    cp_wait0();
    __syncthreads();

    for (int kt = 0; kt < NT; kt++) {
        const int k0 = kt * BN;
        const int cur = kt & 1;
        const uint32_t htbase = sb + OFF_HT + cur * HTBYTES;

        uint32_t sacc[2][4][2];
        #pragma unroll
        for (int mb = 0; mb < 2; mb++)
            #pragma unroll
            for (int jj = 0; jj < 4; jj++) { sacc[mb][jj][0] = 0; sacc[mb][jj][1] = 0; }

        #pragma unroll
        for (int s = 0; s < 4; s++) {
            uint32_t aq0[4], aq1[4];
            ldsm_x4(aq0[0], aq0[1], aq0[2], aq0[3],
                    sb + OFF_Q + aqm0 * PSS + s * 32 + aqkc);
            ldsm_x4(aq1[0], aq1[1], aq1[2], aq1[3],
                    sb + OFF_Q + (aqm0 + 16) * PSS + s * 32 + aqkc);
            #pragma unroll
            for (int nb = 0; nb < 2; nb++) {
                uint32_t addr = sb + OFF_K + (nrowb + nb * 16) * KS + s * 32 + kcb;
                uint32_t b0, b1, b2, b3;
                ldsm_x4(b0, b1, b2, b3, addr);
                mma_fp8h(sacc[0][2 * nb],     aq0, b0, b1);
                mma_fp8h(sacc[0][2 * nb + 1], aq0, b2, b3);
                mma_fp8h(sacc[1][2 * nb],     aq1, b0, b1);
                mma_fp8h(sacc[1][2 * nb + 1], aq1, b2, b3);
            }
        }
        __syncthreads();   // all warps done reading K (single buffer)

        if (kt + 1 < NT) {
            issue_k(sb, tid, (kt + 1) * BN);
            issue_ht(sb, tid, (kt + 1) * BN, cur ^ 1);
            cp_commit();
        }

        {
            const bool dt = (kt == diag_kt);
            #pragma unroll
            for (int mb = 0; mb < 2; mb++) {
                const int row0 = wr * 32 + mb * 16 + g;
                uint32_t hs0 = 0, hs1 = 0;
                #pragma unroll
                for (int jj = 0; jj < 4; jj++) {
                    int col = wq * 32 + jj * 8 + 2 * t;
                    uint32_t r0 = sacc[mb][jj][0];
                    uint32_t r1 = sacc[mb][jj][1];
                    if (dt) {
                        int gcol = k0 + col;
                        int grow0 = q0 + row0, grow1 = grow0 + 8;
                        if (grow0 == gcol)     r0 &= 0xFFFF0000u;
                        if (grow0 == gcol + 1) r0 &= 0x0000FFFFu;
                        if (grow1 == gcol)     r1 &= 0xFFFF0000u;
                        if (grow1 == gcol + 1) r1 &= 0x0000FFFFu;
                    }
                    uint32_t p0 = ex2_h2(r0);
                    uint32_t p1 = ex2_h2(r1);
                    hs0 = hadd2u(hs0, p0);
                    hs1 = hadd2u(hs1, p1);
                    *(uint16_t*)(sm + OFF_P + row0 * PSS + col) = h2_to_e4m3x2(p0);
                    *(uint16_t*)(sm + OFF_P + (row0 + 8) * PSS + col) = h2_to_e4m3x2(p1);
                }
                float2 f0 = h22f2(hs0);
                float2 f1 = h22f2(hs1);
                lsum[2 * mb]     += f0.x + f0.y;
                lsum[2 * mb + 1] += f1.x + f1.y;
            }
        }
        bar_grp(1 + wr);

        #pragma unroll
        for (int s2 = 0; s2 < 4; s2++) {
            uint32_t pa[2][4];
            #pragma unroll
            for (int mb = 0; mb < 2; mb++) {
                uint32_t addr = sb + OFF_P + (wr * 32 + mb * 16 + am) * PSS
                              + s2 * 32 + akc;
                ldsm_x4(pa[mb][0], pa[mb][1], pa[mb][2], pa[mb][3], addr);
            }
            #pragma unroll
            for (int jj = 0; jj < 4; jj++) {
                int nbase = wq * 64 + jj * 16;
                uint32_t addr = htbase + (nbase + hrow) * HTS + s2 * 32 + hkc;
                uint32_t b0, b1, b2, b3;
                ldsm_x4(b0, b1, b2, b3, addr);
                #pragma unroll
                for (int mb = 0; mb < 2; mb++) {
                    mma_fp8h(o16[mb * 8 + jj * 2],     pa[mb], b0, b1);
                    mma_fp8h(o16[mb * 8 + jj * 2 + 1], pa[mb], b2, b3);
                }
            }
        }

        if ((kt & 7) == 7) {
            #pragma unroll
            for (int i = 0; i < 16; i++) {
                om[i][0] = hadd2u(om[i][0], o16[i][0]);
                om[i][1] = hadd2u(om[i][1], o16[i][1]);
                o16[i][0] = 0; o16[i][1] = 0;
            }
        }

        cp_wait0();
        __syncthreads();
    }

    // ---- epilogue ----
    #pragma unroll
    for (int i = 0; i < 4; i++) {
        lsum[i] += __shfl_xor_sync(0xffffffffu, lsum[i], 1);
        lsum[i] += __shfl_xor_sync(0xffffffffu, lsum[i], 2);
    }
    float* Ls = (float*)(sm + OFF_L);
    if (t == 0) {
        int r = wr * 32 + g;
        Ls[wq * 64 + r]      = lsum[0];
        Ls[wq * 64 + r + 8]  = lsum[1];
        Ls[wq * 64 + r + 16] = lsum[2];
        Ls[wq * 64 + r + 24] = lsum[3];
    }
    __syncthreads();

    #pragma unroll
    for (int mb = 0; mb < 2; mb++) {
        int row0 = wr * 32 + mb * 16 + g;
        float invA = 1.f / (Ls[row0] + Ls[64 + row0] + Ls[128 + row0] + Ls[192 + row0]);
        float invB = 1.f / (Ls[row0 + 8] + Ls[64 + row0 + 8] +
                            Ls[128 + row0 + 8] + Ls[192 + row0 + 8]);
        int grow0 = q0 + row0;
        #pragma unroll
        for (int jj = 0; jj < 4; jj++) {
            #pragma unroll
            for (int n8 = 0; n8 < 2; n8++) {
                int col = wq * 64 + jj * 16 + n8 * 8 + 2 * t;
                int idx = mb * 8 + jj * 2 + n8;
                float2 a = h22f2(om[idx][0]);
                float2 b = h22f2(om[idx][1]);
                float2 h0 = *(const float2*)(H + (size_t)grow0 * TT + col);
                float2 h1 = *(const float2*)(H + (size_t)(grow0 + 8) * TT + col);
                float2 o0, o1;
                o0.x = a.x * invA + h0.x;
                o0.y = a.y * invA + h0.y;
                o1.x = b.x * invB + h1.x;
                o1.y = b.y * invB + h1.y;
                *(float2*)(out + (size_t)grow0 * TT + col) = o0;
                *(float2*)(out + (size_t)(grow0 + 8) * TT + col) = o1;
            }
        }
    }
}

// ===========================================================================
extern "C" void kernel_launch(void* const* d_in, const int* in_sizes, int n_in,
                              void* d_out, int out_size) {
    const float* H  = (const float*)d_in[0];
    const float* Wq = (const float*)d_in[1];
    const float* bq = (const float*)d_in[2];
    const float* Wk = (const float*)d_in[3];
    const float* bk = (const float*)d_in[4];
    float* out = (float*)d_out;

    cudaFuncSetAttribute(qk2_kernel,
                         cudaFuncAttributeMaxDynamicSharedMemorySize, QK_SMEM);
    cudaFuncSetAttribute(attn15_kernel,
                         cudaFuncAttributeMaxDynamicSharedMemorySize, ATTN_SMEM);

    qk2_kernel<<<dim3(NN / 128, 2), 256, QK_SMEM>>>(H, Wq, bq, Wk, bk);
    ht_kernel<<<dim3(NN / 32, TT / 32), dim3(32, 8)>>>(H);
    attn15_kernel<<<NN / BM, 256, ATTN_SMEM>>>(H, out);
}

// round 16
// speedup vs baseline: 1.6039x; 1.1602x over previous
#include <cuda_runtime.h>
#include <cuda_bf16.h>
#include <cuda_fp16.h>
#include <cstdint>

#define NN 16384
#define DH 128
#define TT 256
#define QSCALE (0.08838834764831845f * 1.4426950408889634f)  // 1/sqrt(128)*log2e

#define BN 128
#define NT (NN / BN)
#define NBIG 136           // CTAs with 64 q-rows
#define NSMALL 160         // CTAs with 48 q-rows

// ---- attn smem layout (bytes) — fp8 tiles, 2 CTAs/SM ----
#define KS 144
#define HTS 144
#define PSS 144
#define KBYTES (128 * KS)                   // 18432, SINGLE buffer
#define HTBYTES (256 * HTS)                 // 36864, 2 stages
#define OFF_K 0
#define OFF_HT KBYTES                       // 18432
#define OFF_Q (OFF_HT + 2 * HTBYTES)        // 92160 (9216)
#define OFF_P (OFF_Q + 64 * PSS)            // 101376 (9216)
#define OFF_L (OFF_P + 64 * PSS)            // 110592 (8 slices x 64 rows x 4B)
#define ATTN_SMEM (OFF_L + 2048)            // 112640 (x2 = 225280 <= 228KB)

// ---- qk (bf16 tensor GEMM) smem ----
#define QK_HS 528
#define QK_WS 272
#define QK_OFF_W (128 * QK_HS)
#define QK_SMEM (QK_OFF_W + 256 * QK_WS)    // 137216

// device-global scratch
__device__ uint8_t g_Qf[NN * DH];
__device__ uint8_t g_Kf[NN * DH];
__device__ uint8_t g_HfT[(size_t)TT * NN];

// ===========================================================================
// helpers
// ===========================================================================
__device__ __forceinline__ uint32_t smem_u32(const void* p) {
    uint32_t a;
    asm("{ .reg .u64 t; cvta.to.shared.u64 t, %1; cvt.u32.u64 %0, t; }"
        : "=r"(a) : "l"(p));
    return a;
}
__device__ __forceinline__ void ldsm_x4(uint32_t& r0, uint32_t& r1,
                                        uint32_t& r2, uint32_t& r3, uint32_t a) {
    asm volatile("ldmatrix.sync.aligned.m8n8.x4.shared.b16 {%0,%1,%2,%3}, [%4];"
                 : "=r"(r0), "=r"(r1), "=r"(r2), "=r"(r3) : "r"(a));
}
__device__ __forceinline__ void ldsm_x4_t(uint32_t& r0, uint32_t& r1,
                                          uint32_t& r2, uint32_t& r3, uint32_t a) {
    asm volatile("ldmatrix.sync.aligned.m8n8.x4.trans.shared.b16 {%0,%1,%2,%3}, [%4];"
                 : "=r"(r0), "=r"(r1), "=r"(r2), "=r"(r3) : "r"(a));
}
__device__ __forceinline__ void mma16816(float* d, const uint32_t* a,
                                         uint32_t b0, uint32_t b1) {
    asm volatile("mma.sync.aligned.m16n8k16.row.col.f32.bf16.bf16.f32 "
                 "{%0,%1,%2,%3},{%4,%5,%6,%7},{%8,%9},{%0,%1,%2,%3};"
                 : "+f"(d[0]), "+f"(d[1]), "+f"(d[2]), "+f"(d[3])
                 : "r"(a[0]), "r"(a[1]), "r"(a[2]), "r"(a[3]), "r"(b0), "r"(b1));
}
__device__ __forceinline__ void mma_fp8h(uint32_t* d, const uint32_t* a,
                                         uint32_t b0, uint32_t b1) {
    asm volatile("mma.sync.aligned.m16n8k32.row.col.f16.e4m3.e4m3.f16 "
                 "{%0,%1},{%2,%3,%4,%5},{%6,%7},{%0,%1};"
                 : "+r"(d[0]), "+r"(d[1])
                 : "r"(a[0]), "r"(a[1]), "r"(a[2]), "r"(a[3]), "r"(b0), "r"(b1));
}
__device__ __forceinline__ void cp16(uint32_t dst, const void* src) {
    asm volatile("cp.async.cg.shared.global [%0], [%1], 16;"
                 :: "r"(dst), "l"(src) : "memory");
}
__device__ __forceinline__ void cp_commit() {
    asm volatile("cp.async.commit_group;" ::: "memory");
}
__device__ __forceinline__ void cp_wait0() {
    asm volatile("cp.async.wait_group 0;" ::: "memory");
}
__device__ __forceinline__ uint32_t ex2_h2(uint32_t x) {
    uint32_t y;
    asm("ex2.approx.f16x2 %0, %1;" : "=r"(y) : "r"(x));
    return y;
}
__device__ __forceinline__ uint32_t hadd2u(uint32_t a, uint32_t b) {
    uint32_t y;
    asm("add.f16x2 %0, %1, %2;" : "=r"(y) : "r"(a), "r"(b));
    return y;
}
__device__ __forceinline__ float2 h22f2(uint32_t h2) {
    __half2 h = *(__half2*)&h2;
    return __half22float2(h);
}
__device__ __forceinline__ uint16_t h2_to_e4m3x2(uint32_t h2) {
    uint16_t r;
    asm("cvt.rn.satfinite.e4m3x2.f16x2 %0, %1;" : "=h"(r) : "r"(h2));
    return r;
}
__device__ __forceinline__ uint16_t packf8(float lo, float hi) {
    uint16_t r;
    asm("cvt.rn.satfinite.e4m3x2.f32 %0, %1, %2;" : "=h"(r) : "f"(hi), "f"(lo));
    return r;
}

// ===========================================================================
// Kernel 1: bf16 tensor-core projection (unchanged from R15)
// ===========================================================================
__global__ __launch_bounds__(256)
void qk2_kernel(const float* __restrict__ H,
                const float* __restrict__ Wq, const float* __restrict__ bq,
                const float* __restrict__ Wk, const float* __restrict__ bk) {
    extern __shared__ char qsm[];
    const uint32_t sbq = smem_u32(qsm);

    const float* W = blockIdx.y ? Wk : Wq;
    const float* b = blockIdx.y ? bk : bq;
    uint8_t* outp  = blockIdx.y ? g_Kf : g_Qf;
    const float osc = blockIdx.y ? 1.0f : QSCALE;

    const int tid = threadIdx.x;
    const int wid = tid >> 5, lane = tid & 31;
    const int wr = wid >> 1, wc = wid & 1;
    const int g = lane >> 2, t = lane & 3;
    const int bl = lane >> 3, rl = lane & 7;
    const int row0 = blockIdx.x * 128;

    for (int i = tid; i < 128 * 64; i += 256) {
        int r = i >> 6, c4 = i & 63;
        float4 v = *(const float4*)(H + (size_t)(row0 + r) * TT + c4 * 4);
        __nv_bfloat162 a = __floats2bfloat162_rn(v.x, v.y);
        __nv_bfloat162 bb = __floats2bfloat162_rn(v.z, v.w);
        uint2 o; o.x = *(uint32_t*)&a; o.y = *(uint32_t*)&bb;
        *(uint2*)(qsm + r * QK_HS + c4 * 8) = o;
    }
    for (int i = tid; i < 256 * 32; i += 256) {
        int r = i >> 5, c4 = i & 31;
        float4 v = *(const float4*)(W + (size_t)r * DH + c4 * 4);
        __nv_bfloat162 a = __floats2bfloat162_rn(v.x, v.y);
        __nv_bfloat162 bb = __floats2bfloat162_rn(v.z, v.w);
        uint2 o; o.x = *(uint32_t*)&a; o.y = *(uint32_t*)&bb;
        *(uint2*)(qsm + QK_OFF_W + r * QK_WS + c4 * 8) = o;
    }
    __syncthreads();

    const int m0 = wr * 32;
    const int arow = m0 + rl + ((bl & 1) ? 8 : 0);
    const int akc = (bl & 2) ? 16 : 0;
    const int bkr = rl + ((bl & 1) ? 8 : 0);
    const int bn = (bl & 2) ? 8 : 0;

    float acc[16][4];
    #pragma unroll
    for (int i = 0; i < 16; i++)
        #pragma unroll
        for (int j = 0; j < 4; j++) acc[i][j] = 0.f;

    #pragma unroll
    for (int ks = 0; ks < 16; ks++) {
        uint32_t a0[4], a1[4];
        ldsm_x4(a0[0], a0[1], a0[2], a0[3], sbq + arow * QK_HS + ks * 32 + akc);
        ldsm_x4(a1[0], a1[1], a1[2], a1[3],
                sbq + (arow + 16) * QK_HS + ks * 32 + akc);
        #pragma unroll
        for (int jj = 0; jj < 4; jj++) {
            uint32_t addr = sbq + QK_OFF_W + (ks * 16 + bkr) * QK_WS
                          + (wc * 64 + jj * 16 + bn) * 2;
            uint32_t b0, b1, b2, b3;
            ldsm_x4_t(b0, b1, b2, b3, addr);
            mma16816(acc[jj * 2],     a0, b0, b1);
            mma16816(acc[jj * 2 + 1], a0, b2, b3);
            mma16816(acc[8 + jj * 2],     a1, b0, b1);
            mma16816(acc[8 + jj * 2 + 1], a1, b2, b3);
        }
    }

    #pragma unroll
    for (int mb = 0; mb < 2; mb++) {
        int r0 = row0 + m0 + mb * 16 + g;
        #pragma unroll
        for (int jj = 0; jj < 4; jj++) {
            #pragma unroll
            for (int n8 = 0; n8 < 2; n8++) {
                int col = wc * 64 + jj * 16 + n8 * 8 + 2 * t;
                const float* oa = acc[mb * 8 + jj * 2 + n8];
                float b0v = b[col], b1v = b[col + 1];
                *(uint16_t*)&outp[(size_t)r0 * DH + col] =
                    packf8((oa[0] + b0v) * osc, (oa[1] + b1v) * osc);
                *(uint16_t*)&outp[(size_t)(r0 + 8) * DH + col] =
                    packf8((oa[2] + b0v) * osc, (oa[3] + b1v) * osc);
            }
        }
    }
}

// ===========================================================================
// Kernel 2: H -> Hᵀ e4m3 (unchanged)
// ===========================================================================
__global__ __launch_bounds__(256)
void ht_kernel(const float* __restrict__ H) {
    __shared__ float tt[32][33];
    int bx = blockIdx.x * 32, by = blockIdx.y * 32;
    int x = threadIdx.x, y = threadIdx.y;
    #pragma unroll
    for (int i = 0; i < 32; i += 8)
        tt[y + i][x] = H[(size_t)(bx + y + i) * TT + by + x];
    __syncthreads();
    #pragma unroll
    for (int i = 0; i < 32; i += 8) {
        uint16_t r = packf8(tt[x][y + i], 0.f);
        g_HfT[(size_t)(by + y + i) * NN + bx + x] = (uint8_t)(r & 0xff);
    }
}

// ===========================================================================
// Kernel 3: balanced flash attention. Grid 296 = 148x2 slots.
// CTA bid<NBIG: 64 q-rows; else 48. 8 warps, wq = wid (16-key MMA1 slice,
// 32-col MMA2 slice). MB-templated m-block loop (MB m16 blocks).
// ===========================================================================
__device__ __forceinline__ void issue_k(uint32_t sb, int tid, int k0) {
    const uint8_t* src = g_Kf + (size_t)k0 * DH;
    #pragma unroll
    for (int i = tid; i < 1024; i += 256) {
        int r = i >> 3, c = i & 7;
        cp16(sb + OFF_K + r * KS + c * 16, src + r * 128 + c * 16);
    }
}
__device__ __forceinline__ void issue_ht(uint32_t sb, int tid, int k0, int stage) {
    uint32_t dstb = sb + OFF_HT + stage * HTBYTES;
    #pragma unroll
    for (int i = tid; i < 2048; i += 256) {
        int r = i >> 3, c = i & 7;
        cp16(dstb + r * HTS + c * 16, g_HfT + (size_t)r * NN + k0 + c * 16);
    }
}

template <int MB>
__device__ __forceinline__ void attn_run(const float* __restrict__ H,
                                         float* __restrict__ out,
                                         int q0, char* sm, uint32_t sb) {
    const int BM = MB * 16;
    const int tid = threadIdx.x;
    const int wid = tid >> 5, lane = tid & 31;
    const int wq = wid;
    const int g = lane >> 2, t = lane & 3;
    const int bl = lane >> 3, rl = lane & 7;

    // prologue: K(0), HT(0), Q
    issue_k(sb, tid, 0);
    issue_ht(sb, tid, 0, 0);
    {
        const uint8_t* src = g_Qf + (size_t)q0 * DH;
        for (int i = tid; i < BM * 8; i += 256) {
            int r = i >> 3, c = i & 7;
            cp16(sb + OFF_Q + r * PSS + c * 16, src + r * 128 + c * 16);
        }
    }
    cp_commit();

    uint32_t o16[MB * 4][2], om[MB * 4][2];
    #pragma unroll
    for (int i = 0; i < MB * 4; i++) {
        o16[i][0] = 0; o16[i][1] = 0;
        om[i][0] = 0;  om[i][1] = 0;
    }
    float lsum[2 * MB];
    #pragma unroll
    for (int i = 0; i < 2 * MB; i++) lsum[i] = 0.f;

    // lane-constant comps
    const int aqr = rl + ((bl & 1) ? 8 : 0);               // A row comp (Q and P)
    const int aqkc = (bl & 2) ? 16 : 0;
    const int nrowb = wq * 16 + rl + ((bl & 2) ? 8 : 0);   // MMA1 B key row
    const int kcb = (bl & 1) ? 16 : 0;
    const int hrow = rl + ((bl & 2) ? 8 : 0);              // MMA2 B (HT) row comp
    const int hkc = (bl & 1) ? 16 : 0;

    cp_wait0();
    __syncthreads();

    for (int kt = 0; kt < NT; kt++) {
        const int k0 = kt * BN;
        const int cur = kt & 1;
        const uint32_t htbase = sb + OFF_HT + cur * HTBYTES;

        // ---- MMA1: S[BM, 16-key slice]
        uint32_t sacc[MB][2][2];
        #pragma unroll
        for (int mb = 0; mb < MB; mb++)
            #pragma unroll
            for (int jj = 0; jj < 2; jj++) { sacc[mb][jj][0] = 0; sacc[mb][jj][1] = 0; }

        #pragma unroll
        for (int s = 0; s < 4; s++) {
            uint32_t b0, b1, b2, b3;
            ldsm_x4(b0, b1, b2, b3,
                    sb + OFF_K + nrowb * KS + s * 32 + kcb);
            #pragma unroll
            for (int mb = 0; mb < MB; mb++) {
                uint32_t aq[4];
                ldsm_x4(aq[0], aq[1], aq[2], aq[3],
                        sb + OFF_Q + (mb * 16 + aqr) * PSS + s * 32 + aqkc);
                mma_fp8h(sacc[mb][0], aq, b0, b1);
                mma_fp8h(sacc[mb][1], aq, b2, b3);
            }
        }

        // ---- exp, diag->1, row sums, publish P
        {
            const bool dt = (q0 < k0 + BN) && (k0 < q0 + BM);
            #pragma unroll
            for (int mb = 0; mb < MB; mb++) {
                const int row0 = mb * 16 + g;
                uint32_t hs0 = 0, hs1 = 0;
                #pragma unroll
                for (int jj = 0; jj < 2; jj++) {
                    int col = wq * 16 + jj * 8 + 2 * t;
                    uint32_t r0 = sacc[mb][jj][0];
                    uint32_t r1 = sacc[mb][jj][1];
                    if (dt) {
                        int gcol = k0 + col;
                        int grow0 = q0 + row0, grow1 = grow0 + 8;
                        if (grow0 == gcol)     r0 &= 0xFFFF0000u;
                        if (grow0 == gcol + 1) r0 &= 0x0000FFFFu;
                        if (grow1 == gcol)     r1 &= 0xFFFF0000u;
                        if (grow1 == gcol + 1) r1 &= 0x0000FFFFu;
                    }
                    uint32_t p0 = ex2_h2(r0);
                    uint32_t p1 = ex2_h2(r1);
                    hs0 = hadd2u(hs0, p0);
                    hs1 = hadd2u(hs1, p1);
                    *(uint16_t*)(sm + OFF_P + row0 * PSS + col) = h2_to_e4m3x2(p0);
                    *(uint16_t*)(sm + OFF_P + (row0 + 8) * PSS + col) = h2_to_e4m3x2(p1);
                }
                float2 f0 = h22f2(hs0);
                float2 f1 = h22f2(hs1);
                lsum[2 * mb]     += f0.x + f0.y;
                lsum[2 * mb + 1] += f1.x + f1.y;
            }
        }
        __syncthreads();   // K reads done + P visible

        if (kt + 1 < NT) {
            issue_k(sb, tid, (kt + 1) * BN);
            issue_ht(sb, tid, (kt + 1) * BN, cur ^ 1);
            cp_commit();
        }

        // ---- MMA2: O[BM, 32-col slice] += P[BM,128] @ H[128, slice]
        #pragma unroll
        for (int s2 = 0; s2 < 4; s2++) {
            uint32_t pa[MB][4];
            #pragma unroll
            for (int mb = 0; mb < MB; mb++)
                ldsm_x4(pa[mb][0], pa[mb][1], pa[mb][2], pa[mb][3],
                        sb + OFF_P + (mb * 16 + aqr) * PSS + s2 * 32 + aqkc);
            #pragma unroll
            for (int jj = 0; jj < 2; jj++) {
                int nbase = wq * 32 + jj * 16;
                uint32_t b0, b1, b2, b3;
                ldsm_x4(b0, b1, b2, b3,
                        htbase + (nbase + hrow) * HTS + s2 * 32 + hkc);
                #pragma unroll
                for (int mb = 0; mb < MB; mb++) {
                    mma_fp8h(o16[mb * 4 + jj * 2],     pa[mb], b0, b1);
                    mma_fp8h(o16[mb * 4 + jj * 2 + 1], pa[mb], b2, b3);
                }
            }
        }

        if ((kt & 7) == 7) {
            #pragma unroll
            for (int i = 0; i < MB * 4; i++) {
                om[i][0] = hadd2u(om[i][0], o16[i][0]);
                om[i][1] = hadd2u(om[i][1], o16[i][1]);
                o16[i][0] = 0; o16[i][1] = 0;
            }
        }

        cp_wait0();
        __syncthreads();   // next tile ready + all MMA2 reads done
    }

    // ---- epilogue ----
    #pragma unroll
    for (int i = 0; i < 2 * MB; i++) {
        lsum[i] += __shfl_xor_sync(0xffffffffu, lsum[i], 1);
        lsum[i] += __shfl_xor_sync(0xffffffffu, lsum[i], 2);
    }
    float* Ls = (float*)(sm + OFF_L);
    if (t == 0) {
        #pragma unroll
        for (int mb = 0; mb < MB; mb++) {
            Ls[wq * 64 + mb * 16 + g]     = lsum[2 * mb];
            Ls[wq * 64 + mb * 16 + g + 8] = lsum[2 * mb + 1];
        }
    }
    __syncthreads();

    #pragma unroll
    for (int mb = 0; mb < MB; mb++) {
        int row0 = mb * 16 + g;
        float sA = 0.f, sB = 0.f;
        #pragma unroll
        for (int w = 0; w < 8; w++) {
            sA += Ls[w * 64 + row0];
            sB += Ls[w * 64 + row0 + 8];
        }
        float invA = 1.f / sA, invB = 1.f / sB;
        int grow0 = q0 + row0;
        #pragma unroll
        for (int jj = 0; jj < 2; jj++) {
            #pragma unroll
            for (int n8 = 0; n8 < 2; n8++) {
                int col = wq * 32 + jj * 16 + n8 * 8 + 2 * t;
                int idx = mb * 4 + jj * 2 + n8;
                float2 a = h22f2(om[idx][0]);
                float2 b = h22f2(om[idx][1]);
                float2 h0 = *(const float2*)(H + (size_t)grow0 * TT + col);
                float2 h1 = *(const float2*)(H + (size_t)(grow0 + 8) * TT + col);
                float2 o0, o1;
                o0.x = a.x * invA + h0.x;
                o0.y = a.y * invA + h0.y;
                o1.x = b.x * invB + h1.x;
                o1.y = b.y * invB + h1.y;
                *(float2*)(out + (size_t)grow0 * TT + col) = o0;
                *(float2*)(out + (size_t)(grow0 + 8) * TT + col) = o1;
            }
        }
    }
}

__global__ void __launch_bounds__(256, 2)
attn16_kernel(const float* __restrict__ H, float* __restrict__ out) {
    extern __shared__ char sm[];
    const uint32_t sb = smem_u32(sm);
    const int bid = blockIdx.x;
    if (bid < NBIG) {
        attn_run<4>(H, out, bid * 64, sm, sb);
    } else {
        attn_run<3>(H, out, NBIG * 64 + (bid - NBIG) * 48, sm, sb);
    }
}

// ===========================================================================
extern "C" void kernel_launch(void* const* d_in, const int* in_sizes, int n_in,
                              void* d_out, int out_size) {
    const float* H  = (const float*)d_in[0];
    const float* Wq = (const float*)d_in[1];
    const float* bq = (const float*)d_in[2];
    const float* Wk = (const float*)d_in[3];
    const float* bk = (const float*)d_in[4];
    float* out = (float*)d_out;

    cudaFuncSetAttribute(qk2_kernel,
                         cudaFuncAttributeMaxDynamicSharedMemorySize, QK_SMEM);
    cudaFuncSetAttribute(attn16_kernel,
                         cudaFuncAttributeMaxDynamicSharedMemorySize, ATTN_SMEM);

    qk2_kernel<<<dim3(NN / 128, 2), 256, QK_SMEM>>>(H, Wq, bq, Wk, bk);
    ht_kernel<<<dim3(NN / 32, TT / 32), dim3(32, 8)>>>(H);
    attn16_kernel<<<NBIG + NSMALL, 256, ATTN_SMEM>>>(H, out);
}

// round 17
// speedup vs baseline: 1.6041x; 1.0002x over previous
#include <cuda_runtime.h>
#include <cuda_bf16.h>
#include <cuda_fp16.h>
#include <cstdint>

#define NN 16384
#define DH 128
#define TT 256
#define QSCALE (0.08838834764831845f * 1.4426950408889634f)  // 1/sqrt(128)*log2e

#define BN 128
#define NT (NN / BN)
#define NBIG 136           // CTAs with 64 q-rows
#define NSMALL 160         // CTAs with 48 q-rows

// ---- attn smem layout (bytes) — fp8 tiles, 2 CTAs/SM ----
#define KS 144
#define HTS 144
#define PSS 144
#define KBYTES (128 * KS)                   // 18432, SINGLE buffer
#define HTBYTES (256 * HTS)                 // 36864, 2 stages
#define OFF_K 0
#define OFF_HT KBYTES                       // 18432
#define OFF_Q (OFF_HT + 2 * HTBYTES)        // 92160 (9216)
#define OFF_P (OFF_Q + 64 * PSS)            // 101376 (9216)
#define OFF_L (OFF_P + 64 * PSS)            // 110592
#define ATTN_SMEM (OFF_L + 2048)            // 112640 (x2 <= 228KB)

// ---- prep (fused qk GEMM + transpose) smem ----
#define QK_S 272                            // 128 bf16 + 16B pad
#define QK_OFF_W (128 * QK_S)               // 34816
#define PREP_SMEM (2 * 128 * QK_S)          // 69632 (x2 = 139264 <= 228KB)

// device-global scratch
__device__ uint8_t g_Qf[NN * DH];
__device__ uint8_t g_Kf[NN * DH];
__device__ uint8_t g_HfT[(size_t)TT * NN];

// ===========================================================================
// helpers
// ===========================================================================
__device__ __forceinline__ uint32_t smem_u32(const void* p) {
    uint32_t a;
    asm("{ .reg .u64 t; cvta.to.shared.u64 t, %1; cvt.u32.u64 %0, t; }"
        : "=r"(a) : "l"(p));
    return a;
}
__device__ __forceinline__ void ldsm_x4(uint32_t& r0, uint32_t& r1,
                                        uint32_t& r2, uint32_t& r3, uint32_t a) {
    asm volatile("ldmatrix.sync.aligned.m8n8.x4.shared.b16 {%0,%1,%2,%3}, [%4];"
                 : "=r"(r0), "=r"(r1), "=r"(r2), "=r"(r3) : "r"(a));
}
__device__ __forceinline__ void ldsm_x4_t(uint32_t& r0, uint32_t& r1,
                                          uint32_t& r2, uint32_t& r3, uint32_t a) {
    asm volatile("ldmatrix.sync.aligned.m8n8.x4.trans.shared.b16 {%0,%1,%2,%3}, [%4];"
                 : "=r"(r0), "=r"(r1), "=r"(r2), "=r"(r3) : "r"(a));
}
__device__ __forceinline__ void mma16816(float* d, const uint32_t* a,
                                         uint32_t b0, uint32_t b1) {
    asm volatile("mma.sync.aligned.m16n8k16.row.col.f32.bf16.bf16.f32 "
                 "{%0,%1,%2,%3},{%4,%5,%6,%7},{%8,%9},{%0,%1,%2,%3};"
                 : "+f"(d[0]), "+f"(d[1]), "+f"(d[2]), "+f"(d[3])
                 : "r"(a[0]), "r"(a[1]), "r"(a[2]), "r"(a[3]), "r"(b0), "r"(b1));
}
__device__ __forceinline__ void mma_fp8h(uint32_t* d, const uint32_t* a,
                                         uint32_t b0, uint32_t b1) {
    asm volatile("mma.sync.aligned.m16n8k32.row.col.f16.e4m3.e4m3.f16 "
                 "{%0,%1},{%2,%3,%4,%5},{%6,%7},{%0,%1};"
                 : "+r"(d[0]), "+r"(d[1])
                 : "r"(a[0]), "r"(a[1]), "r"(a[2]), "r"(a[3]), "r"(b0), "r"(b1));
}
__device__ __forceinline__ void cp16(uint32_t dst, const void* src) {
    asm volatile("cp.async.cg.shared.global [%0], [%1], 16;"
                 :: "r"(dst), "l"(src) : "memory");
}
__device__ __forceinline__ void cp_commit() {
    asm volatile("cp.async.commit_group;" ::: "memory");
}
__device__ __forceinline__ void cp_wait0() {
    asm volatile("cp.async.wait_group 0;" ::: "memory");
}
__device__ __forceinline__ uint32_t ex2_h2(uint32_t x) {
    uint32_t y;
    asm("ex2.approx.f16x2 %0, %1;" : "=r"(y) : "r"(x));
    return y;
}
__device__ __forceinline__ uint32_t hadd2u(uint32_t a, uint32_t b) {
    uint32_t y;
    asm("add.f16x2 %0, %1, %2;" : "=r"(y) : "r"(a), "r"(b));
    return y;
}
__device__ __forceinline__ float2 h22f2(uint32_t h2) {
    __half2 h = *(__half2*)&h2;
    return __half22float2(h);
}
__device__ __forceinline__ uint16_t h2_to_e4m3x2(uint32_t h2) {
    uint16_t r;
    asm("cvt.rn.satfinite.e4m3x2.f16x2 %0, %1;" : "=h"(r) : "r"(h2));
    return r;
}
__device__ __forceinline__ uint16_t packf8(float lo, float hi) {
    uint16_t r;
    asm("cvt.rn.satfinite.e4m3x2.f32 %0, %1, %2;" : "=h"(r) : "f"(hi), "f"(lo));
    return r;
}

// ===========================================================================
// Kernel 1 (fused prep): blockIdx.y 0/1 -> Q/K bf16 tensor GEMM (K chunked,
// 2 CTAs/SM); blockIdx.y 2 -> H transpose to e4m3 g_HfT.
// ===========================================================================
__global__ void __launch_bounds__(256, 2)
prep_kernel(const float* __restrict__ H,
            const float* __restrict__ Wq, const float* __restrict__ bq,
            const float* __restrict__ Wk, const float* __restrict__ bk) {
    extern __shared__ char qsm[];
    const uint32_t sbq = smem_u32(qsm);
    const int tid = threadIdx.x;
    const int row0 = blockIdx.x * 128;

    if (blockIdx.y == 2) {
        // ---- H transpose: rows [row0, row0+128) -> g_HfT[c][row0+r] ----
        float* tp = (float*)qsm;   // t[32][129]
        for (int c0 = 0; c0 < TT; c0 += 32) {
            #pragma unroll 4
            for (int i = tid; i < 4096; i += 256) {
                int r = i >> 5, c = i & 31;
                tp[c * 129 + r] = H[(size_t)(row0 + r) * TT + c0 + c];
            }
            __syncthreads();
            #pragma unroll 4
            for (int i = tid; i < 4096; i += 256) {
                int c = i >> 7, r = i & 127;
                uint16_t v = packf8(tp[c * 129 + r], 0.f);
                g_HfT[(size_t)(c0 + c) * NN + row0 + r] = (uint8_t)(v & 0xff);
            }
            __syncthreads();
        }
        return;
    }

    // ---- bf16 GEMM: out = (H W + b) * osc, K=256 in 2 chunks of 128 ----
    const float* W = blockIdx.y ? Wk : Wq;
    const float* b = blockIdx.y ? bk : bq;
    uint8_t* outp  = blockIdx.y ? g_Kf : g_Qf;
    const float osc = blockIdx.y ? 1.0f : QSCALE;

    const int wid = tid >> 5, lane = tid & 31;
    const int wr = wid >> 1, wc = wid & 1;
    const int g = lane >> 2, t = lane & 3;
    const int bl = lane >> 3, rl = lane & 7;

    const int m0 = wr * 32;
    const int arow = m0 + rl + ((bl & 1) ? 8 : 0);
    const int akc = (bl & 2) ? 16 : 0;
    const int bkr = rl + ((bl & 1) ? 8 : 0);
    const int bn = (bl & 2) ? 8 : 0;

    float acc[16][4];
    #pragma unroll
    for (int i = 0; i < 16; i++)
        #pragma unroll
        for (int j = 0; j < 4; j++) acc[i][j] = 0.f;

    for (int kc = 0; kc < 2; kc++) {
        // load H chunk (128 rows x 128 cols fp32 -> bf16)
        #pragma unroll 4
        for (int i = tid; i < 128 * 32; i += 256) {
            int r = i >> 5, c4 = i & 31;
            float4 v = *(const float4*)(H + (size_t)(row0 + r) * TT
                                        + kc * 128 + c4 * 4);
            __nv_bfloat162 a = __floats2bfloat162_rn(v.x, v.y);
            __nv_bfloat162 bb = __floats2bfloat162_rn(v.z, v.w);
            uint2 o; o.x = *(uint32_t*)&a; o.y = *(uint32_t*)&bb;
            *(uint2*)(qsm + r * QK_S + c4 * 8) = o;
        }
        // load W chunk (128 k-rows x 128 cols)
        #pragma unroll 4
        for (int i = tid; i < 128 * 32; i += 256) {
            int r = i >> 5, c4 = i & 31;
            float4 v = *(const float4*)(W + (size_t)(kc * 128 + r) * DH + c4 * 4);
            __nv_bfloat162 a = __floats2bfloat162_rn(v.x, v.y);
            __nv_bfloat162 bb = __floats2bfloat162_rn(v.z, v.w);
            uint2 o; o.x = *(uint32_t*)&a; o.y = *(uint32_t*)&bb;
            *(uint2*)(qsm + QK_OFF_W + r * QK_S + c4 * 8) = o;
        }
        __syncthreads();

        #pragma unroll
        for (int ks = 0; ks < 8; ks++) {
            uint32_t a0[4], a1[4];
            ldsm_x4(a0[0], a0[1], a0[2], a0[3],
                    sbq + arow * QK_S + ks * 32 + akc);
            ldsm_x4(a1[0], a1[1], a1[2], a1[3],
                    sbq + (arow + 16) * QK_S + ks * 32 + akc);
            #pragma unroll
            for (int jj = 0; jj < 4; jj++) {
                uint32_t addr = sbq + QK_OFF_W + (ks * 16 + bkr) * QK_S
                              + (wc * 64 + jj * 16 + bn) * 2;
                uint32_t b0, b1, b2, b3;
                ldsm_x4_t(b0, b1, b2, b3, addr);
                mma16816(acc[jj * 2],     a0, b0, b1);
                mma16816(acc[jj * 2 + 1], a0, b2, b3);
                mma16816(acc[8 + jj * 2],     a1, b0, b1);
                mma16816(acc[8 + jj * 2 + 1], a1, b2, b3);
            }
        }
        __syncthreads();   // chunk reads done before reload
    }

    #pragma unroll
    for (int mb = 0; mb < 2; mb++) {
        int r0 = row0 + m0 + mb * 16 + g;
        #pragma unroll
        for (int jj = 0; jj < 4; jj++) {
            #pragma unroll
            for (int n8 = 0; n8 < 2; n8++) {
                int col = wc * 64 + jj * 16 + n8 * 8 + 2 * t;
                const float* oa = acc[mb * 8 + jj * 2 + n8];
                float b0v = b[col], b1v = b[col + 1];
                *(uint16_t*)&outp[(size_t)r0 * DH + col] =
                    packf8((oa[0] + b0v) * osc, (oa[1] + b1v) * osc);
                *(uint16_t*)&outp[(size_t)(r0 + 8) * DH + col] =
                    packf8((oa[2] + b0v) * osc, (oa[3] + b1v) * osc);
            }
        }
    }
}

// ===========================================================================
// Kernel 2: balanced flash attention (unchanged from round 16 winner).
// ===========================================================================
__device__ __forceinline__ void issue_k(uint32_t sb, int tid, int k0) {
    const uint8_t* src = g_Kf + (size_t)k0 * DH;
    #pragma unroll
    for (int i = tid; i < 1024; i += 256) {
        int r = i >> 3, c = i & 7;
        cp16(sb + OFF_K + r * KS + c * 16, src + r * 128 + c * 16);
    }
}
__device__ __forceinline__ void issue_ht(uint32_t sb, int tid, int k0, int stage) {
    uint32_t dstb = sb + OFF_HT + stage * HTBYTES;
    #pragma unroll
    for (int i = tid; i < 2048; i += 256) {
        int r = i >> 3, c = i & 7;
        cp16(dstb + r * HTS + c * 16, g_HfT + (size_t)r * NN + k0 + c * 16);
    }
}

template <int MB>
__device__ __forceinline__ void attn_run(const float* __restrict__ H,
                                         float* __restrict__ out,
                                         int q0, char* sm, uint32_t sb) {
    const int BM = MB * 16;
    const int tid = threadIdx.x;
    const int wid = tid >> 5, lane = tid & 31;
    const int wq = wid;
    const int g = lane >> 2, t = lane & 3;
    const int bl = lane >> 3, rl = lane & 7;

    issue_k(sb, tid, 0);
    issue_ht(sb, tid, 0, 0);
    {
        const uint8_t* src = g_Qf + (size_t)q0 * DH;
        for (int i = tid; i < BM * 8; i += 256) {
            int r = i >> 3, c = i & 7;
            cp16(sb + OFF_Q + r * PSS + c * 16, src + r * 128 + c * 16);
        }
    }
    cp_commit();

    uint32_t o16[MB * 4][2], om[MB * 4][2];
    #pragma unroll
    for (int i = 0; i < MB * 4; i++) {
        o16[i][0] = 0; o16[i][1] = 0;
        om[i][0] = 0;  om[i][1] = 0;
    }
    float lsum[2 * MB];
    #pragma unroll
    for (int i = 0; i < 2 * MB; i++) lsum[i] = 0.f;

    const int aqr = rl + ((bl & 1) ? 8 : 0);
    const int aqkc = (bl & 2) ? 16 : 0;
    const int nrowb = wq * 16 + rl + ((bl & 2) ? 8 : 0);
    const int kcb = (bl & 1) ? 16 : 0;
    const int hrow = rl + ((bl & 2) ? 8 : 0);
    const int hkc = (bl & 1) ? 16 : 0;

    cp_wait0();
    __syncthreads();

    for (int kt = 0; kt < NT; kt++) {
        const int k0 = kt * BN;
        const int cur = kt & 1;
        const uint32_t htbase = sb + OFF_HT + cur * HTBYTES;

        uint32_t sacc[MB][2][2];
        #pragma unroll
        for (int mb = 0; mb < MB; mb++)
            #pragma unroll
            for (int jj = 0; jj < 2; jj++) { sacc[mb][jj][0] = 0; sacc[mb][jj][1] = 0; }

        #pragma unroll
        for (int s = 0; s < 4; s++) {
            uint32_t b0, b1, b2, b3;
            ldsm_x4(b0, b1, b2, b3, sb + OFF_K + nrowb * KS + s * 32 + kcb);
            #pragma unroll
            for (int mb = 0; mb < MB; mb++) {
                uint32_t aq[4];
                ldsm_x4(aq[0], aq[1], aq[2], aq[3],
                        sb + OFF_Q + (mb * 16 + aqr) * PSS + s * 32 + aqkc);
                mma_fp8h(sacc[mb][0], aq, b0, b1);
                mma_fp8h(sacc[mb][1], aq, b2, b3);
            }
        }

        {
            const bool dt = (q0 < k0 + BN) && (k0 < q0 + BM);
            #pragma unroll
            for (int mb = 0; mb < MB; mb++) {
                const int row0 = mb * 16 + g;
                uint32_t hs0 = 0, hs1 = 0;
                #pragma unroll
                for (int jj = 0; jj < 2; jj++) {
                    int col = wq * 16 + jj * 8 + 2 * t;
                    uint32_t r0 = sacc[mb][jj][0];
                    uint32_t r1 = sacc[mb][jj][1];
                    if (dt) {
                        int gcol = k0 + col;
                        int grow0 = q0 + row0, grow1 = grow0 + 8;
                        if (grow0 == gcol)     r0 &= 0xFFFF0000u;
                        if (grow0 == gcol + 1) r0 &= 0x0000FFFFu;
                        if (grow1 == gcol)     r1 &= 0xFFFF0000u;
                        if (grow1 == gcol + 1) r1 &= 0x0000FFFFu;
                    }
                    uint32_t p0 = ex2_h2(r0);
                    uint32_t p1 = ex2_h2(r1);
                    hs0 = hadd2u(hs0, p0);
                    hs1 = hadd2u(hs1, p1);
                    *(uint16_t*)(sm + OFF_P + row0 * PSS + col) = h2_to_e4m3x2(p0);
                    *(uint16_t*)(sm + OFF_P + (row0 + 8) * PSS + col) = h2_to_e4m3x2(p1);
                }
                float2 f0 = h22f2(hs0);
                float2 f1 = h22f2(hs1);
                lsum[2 * mb]     += f0.x + f0.y;
                lsum[2 * mb + 1] += f1.x + f1.y;
            }
        }
        __syncthreads();

        if (kt + 1 < NT) {
            issue_k(sb, tid, (kt + 1) * BN);
            issue_ht(sb, tid, (kt + 1) * BN, cur ^ 1);
            cp_commit();
        }

        #pragma unroll
        for (int s2 = 0; s2 < 4; s2++) {
            uint32_t pa[MB][4];
            #pragma unroll
            for (int mb = 0; mb < MB; mb++)
                ldsm_x4(pa[mb][0], pa[mb][1], pa[mb][2], pa[mb][3],
                        sb + OFF_P + (mb * 16 + aqr) * PSS + s2 * 32 + aqkc);
            #pragma unroll
            for (int jj = 0; jj < 2; jj++) {
                int nbase = wq * 32 + jj * 16;
                uint32_t b0, b1, b2, b3;
                ldsm_x4(b0, b1, b2, b3,
                        htbase + (nbase + hrow) * HTS + s2 * 32 + hkc);
                #pragma unroll
                for (int mb = 0; mb < MB; mb++) {
                    mma_fp8h(o16[mb * 4 + jj * 2],     pa[mb], b0, b1);
                    mma_fp8h(o16[mb * 4 + jj * 2 + 1], pa[mb], b2, b3);
                }
            }
        }

        if ((kt & 7) == 7) {
            #pragma unroll
            for (int i = 0; i < MB * 4; i++) {
                om[i][0] = hadd2u(om[i][0], o16[i][0]);
                om[i][1] = hadd2u(om[i][1], o16[i][1]);
                o16[i][0] = 0; o16[i][1] = 0;
            }
        }

        cp_wait0();
        __syncthreads();
    }

    #pragma unroll
    for (int i = 0; i < 2 * MB; i++) {
        lsum[i] += __shfl_xor_sync(0xffffffffu, lsum[i], 1);
        lsum[i] += __shfl_xor_sync(0xffffffffu, lsum[i], 2);
    }
    float* Ls = (float*)(sm + OFF_L);
    if (t == 0) {
        #pragma unroll
        for (int mb = 0; mb < MB; mb++) {
            Ls[wq * 64 + mb * 16 + g]     = lsum[2 * mb];
            Ls[wq * 64 + mb * 16 + g + 8] = lsum[2 * mb + 1];
        }
    }
    __syncthreads();

    #pragma unroll
    for (int mb = 0; mb < MB; mb++) {
        int row0 = mb * 16 + g;
        float sA = 0.f, sB = 0.f;
        #pragma unroll
        for (int w = 0; w < 8; w++) {
            sA += Ls[w * 64 + row0];
            sB += Ls[w * 64 + row0 + 8];
        }
        float invA = 1.f / sA, invB = 1.f / sB;
        int grow0 = q0 + row0;
        #pragma unroll
        for (int jj = 0; jj < 2; jj++) {
            #pragma unroll
            for (int n8 = 0; n8 < 2; n8++) {
                int col = wq * 32 + jj * 16 + n8 * 8 + 2 * t;
                int idx = mb * 4 + jj * 2 + n8;
                float2 a = h22f2(om[idx][0]);
                float2 b = h22f2(om[idx][1]);
                float2 h0 = *(const float2*)(H + (size_t)grow0 * TT + col);
                float2 h1 = *(const float2*)(H + (size_t)(grow0 + 8) * TT + col);
                float2 o0, o1;
                o0.x = a.x * invA + h0.x;
                o0.y = a.y * invA + h0.y;
                o1.x = b.x * invB + h1.x;
                o1.y = b.y * invB + h1.y;
                *(float2*)(out + (size_t)grow0 * TT + col) = o0;
                *(float2*)(out + (size_t)(grow0 + 8) * TT + col) = o1;
            }
        }
    }
}

__global__ void __launch_bounds__(256, 2)
attn17_kernel(const float* __restrict__ H, float* __restrict__ out) {
    extern __shared__ char sm[];
    const uint32_t sb = smem_u32(sm);
    const int bid = blockIdx.x;
    if (bid < NBIG) {
        attn_run<4>(H, out, bid * 64, sm, sb);
    } else {
        attn_run<3>(H, out, NBIG * 64 + (bid - NBIG) * 48, sm, sb);
    }
}

// ===========================================================================
extern "C" void kernel_launch(void* const* d_in, const int* in_sizes, int n_in,
                              void* d_out, int out_size) {
    const float* H  = (const float*)d_in[0];
    const float* Wq = (const float*)d_in[1];
    const float* bq = (const float*)d_in[2];
    const float* Wk = (const float*)d_in[3];
    const float* bk = (const float*)d_in[4];
    float* out = (float*)d_out;

    cudaFuncSetAttribute(prep_kernel,
                         cudaFuncAttributeMaxDynamicSharedMemorySize, PREP_SMEM);
    cudaFuncSetAttribute(attn17_kernel,
                         cudaFuncAttributeMaxDynamicSharedMemorySize, ATTN_SMEM);

    prep_kernel<<<dim3(NN / 128, 3), 256, PREP_SMEM>>>(H, Wq, bq, Wk, bk);
    attn17_kernel<<<NBIG + NSMALL, 256, ATTN_SMEM>>>(H, out);
}